// round 1
// baseline (speedup 1.0000x reference)
#include <cuda_runtime.h>

#define B_  512
#define T_  128
#define F_  512
#define H_  512
#define G3  1536   // 3*H

// Scratch (device globals: allocation-free per harness rules)
__device__ float g_xproj[(size_t)B_ * T_ * G3];   // [T*B, 3H], m = t*B + b
__device__ float g_hp[B_ * G3];                   // recurrent projection
__device__ float g_h[2][B_ * H_];                 // ping-pong hidden state

// ---------------------------------------------------------------------------
// zero h0
// ---------------------------------------------------------------------------
__global__ void zero_h_kernel() {
    int i = blockIdx.x * blockDim.x + threadIdx.x;
    if (i < B_ * H_) g_h[0][i] = 0.0f;
}

// ---------------------------------------------------------------------------
// Big input-projection GEMM:
//   g_xproj[m, n] = sum_f x[b, t, f] * kernel[f, n] + bias_i[n],  m = t*B + b
// Tiles: BM=128, BN=64, BK=16, 256 threads, thread tile 8x4.
// ---------------------------------------------------------------------------
__global__ void __launch_bounds__(256)
gemm_xproj_kernel(const float* __restrict__ X,
                  const float* __restrict__ W,
                  const float* __restrict__ bias)
{
    const int BM = 128, BN = 64, BK = 16;
    __shared__ float As[BK][BM];   // transposed: As[k][m]
    __shared__ float Bs[BK][BN];

    const int tid = threadIdx.x;
    const int m0  = blockIdx.y * BM;
    const int n0  = blockIdx.x * BN;

    const int tx = tid & 15;   // 16 col groups * 4 cols = 64
    const int ty = tid >> 4;   // 16 row groups * 8 rows = 128

    float acc[8][4];
#pragma unroll
    for (int i = 0; i < 8; ++i)
#pragma unroll
        for (int j = 0; j < 4; ++j) acc[i][j] = 0.0f;

    for (int k0 = 0; k0 < F_; k0 += BK) {
        // Load A tile (128x16): 512 float4 slots, 2 per thread.
#pragma unroll
        for (int it = 0; it < 2; ++it) {
            int s  = it * 256 + tid;
            int ar = s >> 2;          // 0..127
            int ac = (s & 3) << 2;    // 0,4,8,12
            int m  = m0 + ar;
            int b  = m & (B_ - 1);
            int t  = m >> 9;          // m / 512
            const float4 v = *(const float4*)(X + (size_t)b * T_ * F_ +
                                              (size_t)t * F_ + k0 + ac);
            As[ac + 0][ar] = v.x;
            As[ac + 1][ar] = v.y;
            As[ac + 2][ar] = v.z;
            As[ac + 3][ar] = v.w;
        }
        // Load B tile (16x64): 256 float4, 1 per thread.
        {
            int br = tid >> 4;        // 0..15
            int bc = (tid & 15) << 2; // 0..60
            const float4 v = *(const float4*)(W + (size_t)(k0 + br) * G3 + n0 + bc);
            *(float4*)&Bs[br][bc] = v;
        }
        __syncthreads();

#pragma unroll
        for (int k = 0; k < BK; ++k) {
            float4 a0 = *(const float4*)&As[k][ty * 8];
            float4 a1 = *(const float4*)&As[k][ty * 8 + 4];
            float4 b4 = *(const float4*)&Bs[k][tx * 4];
            float a[8] = {a0.x, a0.y, a0.z, a0.w, a1.x, a1.y, a1.z, a1.w};
            float bb[4] = {b4.x, b4.y, b4.z, b4.w};
#pragma unroll
            for (int i = 0; i < 8; ++i)
#pragma unroll
                for (int j = 0; j < 4; ++j)
                    acc[i][j] = fmaf(a[i], bb[j], acc[i][j]);
        }
        __syncthreads();
    }

    // Epilogue: add bias, store row-major [M, G3].
    const float4 bv = *(const float4*)(bias + n0 + tx * 4);
#pragma unroll
    for (int i = 0; i < 8; ++i) {
        int m = m0 + ty * 8 + i;
        float4 o;
        o.x = acc[i][0] + bv.x;
        o.y = acc[i][1] + bv.y;
        o.z = acc[i][2] + bv.z;
        o.w = acc[i][3] + bv.w;
        *(float4*)&g_xproj[(size_t)m * G3 + n0 + tx * 4] = o;
    }
}

// ---------------------------------------------------------------------------
// Recurrent GEMM: g_hp[b, n] = sum_k h[b, k] * rkernel[k, n] + bias_r[n]
// Tiles: BM=64, BN=64, BK=16, 256 threads, thread tile 4x4. 192 blocks.
// ---------------------------------------------------------------------------
__global__ void __launch_bounds__(256)
step_gemm_kernel(const float* __restrict__ W,
                 const float* __restrict__ bias,
                 int cur)
{
    const int BM = 64, BN = 64, BK = 16;
    __shared__ float As[BK][BM];
    __shared__ float Bs[BK][BN];

    const float* __restrict__ Hm = g_h[cur];

    const int tid = threadIdx.x;
    const int m0  = blockIdx.y * BM;
    const int n0  = blockIdx.x * BN;

    const int tx = tid & 15;   // 16 * 4 = 64 cols
    const int ty = tid >> 4;   // 16 * 4 = 64 rows

    float acc[4][4];
#pragma unroll
    for (int i = 0; i < 4; ++i)
#pragma unroll
        for (int j = 0; j < 4; ++j) acc[i][j] = 0.0f;

    for (int k0 = 0; k0 < H_; k0 += BK) {
        // A tile (64x16): 256 float4, 1 per thread.
        {
            int ar = tid >> 2;        // 0..63
            int ac = (tid & 3) << 2;  // 0,4,8,12
            const float4 v = *(const float4*)(Hm + (size_t)(m0 + ar) * H_ + k0 + ac);
            As[ac + 0][ar] = v.x;
            As[ac + 1][ar] = v.y;
            As[ac + 2][ar] = v.z;
            As[ac + 3][ar] = v.w;
        }
        // B tile (16x64)
        {
            int br = tid >> 4;
            int bc = (tid & 15) << 2;
            const float4 v = *(const float4*)(W + (size_t)(k0 + br) * G3 + n0 + bc);
            *(float4*)&Bs[br][bc] = v;
        }
        __syncthreads();

#pragma unroll
        for (int k = 0; k < BK; ++k) {
            float4 a4 = *(const float4*)&As[k][ty * 4];
            float4 b4 = *(const float4*)&Bs[k][tx * 4];
            float a[4]  = {a4.x, a4.y, a4.z, a4.w};
            float bb[4] = {b4.x, b4.y, b4.z, b4.w};
#pragma unroll
            for (int i = 0; i < 4; ++i)
#pragma unroll
                for (int j = 0; j < 4; ++j)
                    acc[i][j] = fmaf(a[i], bb[j], acc[i][j]);
        }
        __syncthreads();
    }

    const float4 bv = *(const float4*)(bias + n0 + tx * 4);
#pragma unroll
    for (int i = 0; i < 4; ++i) {
        int m = m0 + ty * 4 + i;
        float4 o;
        o.x = acc[i][0] + bv.x;
        o.y = acc[i][1] + bv.y;
        o.z = acc[i][2] + bv.z;
        o.w = acc[i][3] + bv.w;
        *(float4*)&g_hp[(size_t)m * G3 + n0 + tx * 4] = o;
    }
}

// ---------------------------------------------------------------------------
// Gates: z,r,hh -> h_new
// ---------------------------------------------------------------------------
__global__ void gate_kernel(int t, int cur)
{
    int i = blockIdx.x * blockDim.x + threadIdx.x;
    if (i >= B_ * H_) return;
    int b = i >> 9;          // / 512
    int n = i & (H_ - 1);

    const float* __restrict__ xr = g_xproj + (size_t)t * B_ * G3 + (size_t)b * G3;
    const float* __restrict__ hr = g_hp + (size_t)b * G3;

    float zi = xr[n]          + hr[n];
    float ri = xr[n + H_]     + hr[n + H_];
    float z  = 1.0f / (1.0f + expf(-zi));
    float r  = 1.0f / (1.0f + expf(-ri));
    float hh = tanhf(xr[n + 2 * H_] + r * hr[n + 2 * H_]);
    float h  = g_h[cur][i];
    g_h[cur ^ 1][i] = z * h + (1.0f - z) * hh;
}

// ---------------------------------------------------------------------------
// Dense head: out[b] = dot(h[b,:], w) + b0
// ---------------------------------------------------------------------------
__global__ void dense_kernel(int cur,
                             const float* __restrict__ w,
                             const float* __restrict__ b0,
                             float* __restrict__ out)
{
    __shared__ float red[4];
    int b   = blockIdx.x;
    int tid = threadIdx.x;   // 128
    const float* __restrict__ hrow = g_h[cur] + (size_t)b * H_;

    float s = 0.0f;
    for (int n = tid; n < H_; n += 128) s = fmaf(hrow[n], w[n], s);
#pragma unroll
    for (int o = 16; o > 0; o >>= 1) s += __shfl_down_sync(0xffffffffu, s, o);
    if ((tid & 31) == 0) red[tid >> 5] = s;
    __syncthreads();
    if (tid == 0) out[b] = red[0] + red[1] + red[2] + red[3] + b0[0];
}

// ---------------------------------------------------------------------------
// Launch
// ---------------------------------------------------------------------------
extern "C" void kernel_launch(void* const* d_in, const int* in_sizes, int n_in,
                              void* d_out, int out_size)
{
    const float* x       = (const float*)d_in[0];
    const float* kernel  = (const float*)d_in[1];
    const float* rkernel = (const float*)d_in[2];
    const float* bias_i  = (const float*)d_in[3];
    const float* bias_r  = (const float*)d_in[4];
    const float* dense_w = (const float*)d_in[5];
    const float* dense_b = (const float*)d_in[6];
    float* out = (float*)d_out;

    zero_h_kernel<<<(B_ * H_ + 511) / 512, 512>>>();

    dim3 gbig(G3 / 64, (B_ * T_) / 128);   // (24, 512)
    gemm_xproj_kernel<<<gbig, 256>>>(x, kernel, bias_i);

    dim3 gstep(G3 / 64, B_ / 64);          // (24, 8) = 192 blocks
    int cur = 0;
    for (int t = 0; t < T_; ++t) {
        step_gemm_kernel<<<gstep, 256>>>(rkernel, bias_r, cur);
        gate_kernel<<<(B_ * H_ + 255) / 256, 256>>>(t, cur);
        cur ^= 1;
    }

    dense_kernel<<<B_, 128>>>(cur, dense_w, dense_b, out);
}

// round 5
// speedup vs baseline: 1.7743x; 1.7743x over previous
#include <cuda_runtime.h>
#include <cuda_bf16.h>
#include <cstdint>

#define Bb   512
#define Tt   128
#define Ff   512
#define Hh   512
#define G3c  1536
#define MBIG (Bb * Tt)

// ---------------------------------------------------------------------------
// Device-global scratch
// ---------------------------------------------------------------------------
__device__ float g_xproj[(size_t)MBIG * G3c];      // [T*B, 3H], m = t*B + b
__device__ float g_hp[Bb * G3c];                   // recurrent projection
__device__ float g_h[2 * Bb * Hh];                 // ping-pong hidden (fp32)
__device__ __nv_bfloat16 g_hhi[2 * Bb * Hh];
__device__ __nv_bfloat16 g_hlo[2 * Bb * Hh];
__device__ __nv_bfloat16 g_xhi[(size_t)MBIG * Ff]; // [m, f]
__device__ __nv_bfloat16 g_xlo[(size_t)MBIG * Ff];
__device__ __nv_bfloat16 g_wthi[G3c * Ff];         // kernel^T  [N=3H, K=F]
__device__ __nv_bfloat16 g_wtlo[G3c * Ff];
__device__ __nv_bfloat16 g_rthi[G3c * Hh];         // rkernel^T [N=3H, K=H]
__device__ __nv_bfloat16 g_rtlo[G3c * Hh];

// ---------------------------------------------------------------------------
// Helpers
// ---------------------------------------------------------------------------
__device__ __forceinline__ void mma16816(float* d, const uint32_t* a, const uint32_t* b) {
    asm volatile(
        "mma.sync.aligned.m16n8k16.row.col.f32.bf16.bf16.f32 "
        "{%0,%1,%2,%3}, {%4,%5,%6,%7}, {%8,%9}, {%0,%1,%2,%3};"
        : "+f"(d[0]), "+f"(d[1]), "+f"(d[2]), "+f"(d[3])
        : "r"(a[0]), "r"(a[1]), "r"(a[2]), "r"(a[3]), "r"(b[0]), "r"(b[1]));
}
__device__ __forceinline__ void split_bf16(float v, __nv_bfloat16& hi, __nv_bfloat16& lo) {
    hi = __float2bfloat16(v);
    lo = __float2bfloat16(v - __bfloat162float(hi));
}

// ---------------------------------------------------------------------------
// Prep kernels
// ---------------------------------------------------------------------------
__global__ void prep_x_kernel(const float* __restrict__ x) {
    int m = blockIdx.x;
    int b = m & (Bb - 1);
    int t = m >> 9;
    const float4 v = ((const float4*)(x + ((size_t)b * Tt + t) * Ff))[threadIdx.x];
    size_t o = (size_t)m * Ff + threadIdx.x * 4;
    __nv_bfloat16 h0, l0, h1, l1, h2, l2, h3, l3;
    split_bf16(v.x, h0, l0); split_bf16(v.y, h1, l1);
    split_bf16(v.z, h2, l2); split_bf16(v.w, h3, l3);
    *(__nv_bfloat162*)(g_xhi + o)     = __nv_bfloat162(h0, h1);
    *(__nv_bfloat162*)(g_xhi + o + 2) = __nv_bfloat162(h2, h3);
    *(__nv_bfloat162*)(g_xlo + o)     = __nv_bfloat162(l0, l1);
    *(__nv_bfloat162*)(g_xlo + o + 2) = __nv_bfloat162(l2, l3);
}

__global__ void prep_w_kernel(const float* __restrict__ W, int which) {
    int n = blockIdx.x * 256 + threadIdx.x;
    int k = blockIdx.y;
    float v = W[(size_t)k * G3c + n];
    __nv_bfloat16 hi, lo;
    split_bf16(v, hi, lo);
    size_t o = (size_t)n * 512 + k;
    if (which == 0) { g_wthi[o] = hi; g_wtlo[o] = lo; }
    else            { g_rthi[o] = hi; g_rtlo[o] = lo; }
}

__global__ void zero_h_kernel() {
    int i = blockIdx.x * blockDim.x + threadIdx.x;
    if (i < Bb * Hh) {
        g_h[i]   = 0.0f;
        g_hhi[i] = __float2bfloat16(0.0f);
        g_hlo[i] = __float2bfloat16(0.0f);
    }
}

// ---------------------------------------------------------------------------
// bf16x3 GEMM on mma.sync (HMMA), explicit LDS fragment loads (no ldmatrix):
//   C[M, G3c] = Ahi/Alo [M, 512] @ (Bhi/Blo [N, 512])^T + bias
// BM templated: 128 (xproj) / 64 (step). BN = 64, BK = 32, 256 threads.
// Smem rows padded to 40 elements (80B = 20 banks -> conflict-free frags).
// ---------------------------------------------------------------------------
template <int BM>
__global__ void __launch_bounds__(256)
gemm_mma(const __nv_bfloat16* __restrict__ Ahi,
         const __nv_bfloat16* __restrict__ Alo,
         const __nv_bfloat16* __restrict__ Bhi,
         const __nv_bfloat16* __restrict__ Blo,
         const float* __restrict__ bias,
         float* __restrict__ C)
{
    constexpr int WARPS_M = BM / 32;      // 4 or 2
    constexpr int WARPS_N = 8 / WARPS_M;  // 2 or 4
    constexpr int NSPAN   = 64 / WARPS_N; // 32 or 16
    constexpr int NT      = NSPAN / 8;    // 4 or 2
    constexpr int PAD     = 40;           // row stride in elements

    __shared__ __align__(128) __nv_bfloat16 sAhi[BM * PAD];
    __shared__ __align__(128) __nv_bfloat16 sAlo[BM * PAD];
    __shared__ __align__(128) __nv_bfloat16 sBhi[64 * PAD];
    __shared__ __align__(128) __nv_bfloat16 sBlo[64 * PAD];

    const int tid = threadIdx.x;
    const int wid = tid >> 5, lane = tid & 31;
    const int wm = wid & (WARPS_M - 1);
    const int wn = wid / WARPS_M;
    const int m0 = blockIdx.y * BM, n0 = blockIdx.x * 64;

    const int lr = lane >> 2;        // 0..7
    const int lc = (lane & 3) * 2;   // 0,2,4,6

    float acc[2][NT][4];
#pragma unroll
    for (int i = 0; i < 2; ++i)
#pragma unroll
        for (int j = 0; j < NT; ++j)
#pragma unroll
            for (int q = 0; q < 4; ++q) acc[i][j][q] = 0.0f;

    for (int kb = 0; kb < 16; ++kb) {
        const int k0 = kb * 32;
        // ---- stage A tile (BM x 32 bf16 = BM rows x 4 16B-chunks) ----
#pragma unroll
        for (int it = 0; it < BM / 64; ++it) {
            int idx = it * 256 + tid;     // over BM*4 chunks
            int r = idx >> 2, c = idx & 3;
            size_t go = (size_t)(m0 + r) * 512 + k0 + c * 8;
            *(uint4*)&sAhi[r * PAD + c * 8] = *(const uint4*)(Ahi + go);
            *(uint4*)&sAlo[r * PAD + c * 8] = *(const uint4*)(Alo + go);
        }
        // ---- stage B tile (64 x 32 = 256 chunks, 1 per thread) ----
        {
            int r = tid >> 2, c = tid & 3;
            size_t go = (size_t)(n0 + r) * 512 + k0 + c * 8;
            *(uint4*)&sBhi[r * PAD + c * 8] = *(const uint4*)(Bhi + go);
            *(uint4*)&sBlo[r * PAD + c * 8] = *(const uint4*)(Blo + go);
        }
        __syncthreads();

#pragma unroll
        for (int ks = 0; ks < 2; ++ks) {
            const int ko = ks * 16 + lc;
            uint32_t ahi[2][4], alo[2][4], bhi[NT][2], blo[NT][2];
#pragma unroll
            for (int mt = 0; mt < 2; ++mt) {
                int o = (wm * 32 + mt * 16 + lr) * PAD + ko;
                ahi[mt][0] = *(const uint32_t*)&sAhi[o];
                ahi[mt][1] = *(const uint32_t*)&sAhi[o + 8 * PAD];
                ahi[mt][2] = *(const uint32_t*)&sAhi[o + 8];
                ahi[mt][3] = *(const uint32_t*)&sAhi[o + 8 * PAD + 8];
                alo[mt][0] = *(const uint32_t*)&sAlo[o];
                alo[mt][1] = *(const uint32_t*)&sAlo[o + 8 * PAD];
                alo[mt][2] = *(const uint32_t*)&sAlo[o + 8];
                alo[mt][3] = *(const uint32_t*)&sAlo[o + 8 * PAD + 8];
            }
#pragma unroll
            for (int nt = 0; nt < NT; ++nt) {
                int o = (wn * NSPAN + nt * 8 + lr) * PAD + ko;
                bhi[nt][0] = *(const uint32_t*)&sBhi[o];
                bhi[nt][1] = *(const uint32_t*)&sBhi[o + 8];
                blo[nt][0] = *(const uint32_t*)&sBlo[o];
                blo[nt][1] = *(const uint32_t*)&sBlo[o + 8];
            }
#pragma unroll
            for (int mt = 0; mt < 2; ++mt)
#pragma unroll
                for (int nt = 0; nt < NT; ++nt) {
                    mma16816(acc[mt][nt], ahi[mt], bhi[nt]);
                    mma16816(acc[mt][nt], ahi[mt], blo[nt]);
                    mma16816(acc[mt][nt], alo[mt], bhi[nt]);
                }
        }
        __syncthreads();
    }

    // ---- epilogue: add bias, write fp32 ----
#pragma unroll
    for (int mt = 0; mt < 2; ++mt) {
#pragma unroll
        for (int nt = 0; nt < NT; ++nt) {
            int n = n0 + wn * NSPAN + nt * 8 + (lane & 3) * 2;
            int mA = m0 + wm * 32 + mt * 16 + (lane >> 2);
            int mB = mA + 8;
            float bx = bias[n], by = bias[n + 1];
            float2 o0 = make_float2(acc[mt][nt][0] + bx, acc[mt][nt][1] + by);
            float2 o1 = make_float2(acc[mt][nt][2] + bx, acc[mt][nt][3] + by);
            *(float2*)(C + (size_t)mA * G3c + n) = o0;
            *(float2*)(C + (size_t)mB * G3c + n) = o1;
        }
    }
}

// ---------------------------------------------------------------------------
// Gates
// ---------------------------------------------------------------------------
__device__ __forceinline__ float sigm(float x) { return 1.0f / (1.0f + __expf(-x)); }
__device__ __forceinline__ float tanh_fast(float x) {
    return 1.0f - 2.0f / (__expf(2.0f * x) + 1.0f);
}

__global__ void gate_kernel(int t, int cur) {
    int i4 = blockIdx.x * blockDim.x + threadIdx.x;
    int i = i4 * 4;
    int b = i >> 9;
    int n = i & (Hh - 1);

    const float* xr = g_xproj + (size_t)t * Bb * G3c + (size_t)b * G3c;
    const float* hr = g_hp + (size_t)b * G3c;

    float4 xz = *(const float4*)(xr + n);
    float4 xg = *(const float4*)(xr + n + Hh);
    float4 xh = *(const float4*)(xr + n + 2 * Hh);
    float4 hz = *(const float4*)(hr + n);
    float4 hg = *(const float4*)(hr + n + Hh);
    float4 hhp = *(const float4*)(hr + n + 2 * Hh);
    float4 hv = *(const float4*)(g_h + (size_t)cur * Bb * Hh + i);

    float hn[4];
    {
        float z0 = sigm(xz.x + hz.x), r0 = sigm(xg.x + hg.x);
        hn[0] = z0 * hv.x + (1.0f - z0) * tanh_fast(xh.x + r0 * hhp.x);
        float z1 = sigm(xz.y + hz.y), r1 = sigm(xg.y + hg.y);
        hn[1] = z1 * hv.y + (1.0f - z1) * tanh_fast(xh.y + r1 * hhp.y);
        float z2 = sigm(xz.z + hz.z), r2 = sigm(xg.z + hg.z);
        hn[2] = z2 * hv.z + (1.0f - z2) * tanh_fast(xh.z + r2 * hhp.z);
        float z3 = sigm(xz.w + hz.w), r3 = sigm(xg.w + hg.w);
        hn[3] = z3 * hv.w + (1.0f - z3) * tanh_fast(xh.w + r3 * hhp.w);
    }

    size_t oo = (size_t)(cur ^ 1) * Bb * Hh + i;
    *(float4*)(g_h + oo) = make_float4(hn[0], hn[1], hn[2], hn[3]);

    __nv_bfloat16 h0, l0, h1, l1, h2, l2, h3, l3;
    split_bf16(hn[0], h0, l0); split_bf16(hn[1], h1, l1);
    split_bf16(hn[2], h2, l2); split_bf16(hn[3], h3, l3);
    *(__nv_bfloat162*)(g_hhi + oo)     = __nv_bfloat162(h0, h1);
    *(__nv_bfloat162*)(g_hhi + oo + 2) = __nv_bfloat162(h2, h3);
    *(__nv_bfloat162*)(g_hlo + oo)     = __nv_bfloat162(l0, l1);
    *(__nv_bfloat162*)(g_hlo + oo + 2) = __nv_bfloat162(l2, l3);
}

// ---------------------------------------------------------------------------
// Dense head
// ---------------------------------------------------------------------------
__global__ void dense_kernel(int cur,
                             const float* __restrict__ w,
                             const float* __restrict__ b0,
                             float* __restrict__ out)
{
    __shared__ float red[4];
    int b = blockIdx.x;
    int tid = threadIdx.x;
    const float* hrow = g_h + (size_t)cur * Bb * Hh + (size_t)b * Hh;

    float s = 0.0f;
    for (int n = tid; n < Hh; n += 128) s = fmaf(hrow[n], w[n], s);
#pragma unroll
    for (int o = 16; o > 0; o >>= 1) s += __shfl_down_sync(0xffffffffu, s, o);
    if ((tid & 31) == 0) red[tid >> 5] = s;
    __syncthreads();
    if (tid == 0) out[b] = red[0] + red[1] + red[2] + red[3] + b0[0];
}

// ---------------------------------------------------------------------------
// Launch
// ---------------------------------------------------------------------------
extern "C" void kernel_launch(void* const* d_in, const int* in_sizes, int n_in,
                              void* d_out, int out_size)
{
    const float* x       = (const float*)d_in[0];
    const float* kernel  = (const float*)d_in[1];
    const float* rkernel = (const float*)d_in[2];
    const float* bias_i  = (const float*)d_in[3];
    const float* bias_r  = (const float*)d_in[4];
    const float* dense_w = (const float*)d_in[5];
    const float* dense_b = (const float*)d_in[6];
    float* out = (float*)d_out;

    void *p_xhi, *p_xlo, *p_wthi, *p_wtlo, *p_rthi, *p_rtlo, *p_xproj, *p_hp, *p_hhi, *p_hlo;
    cudaGetSymbolAddress(&p_xhi, g_xhi);
    cudaGetSymbolAddress(&p_xlo, g_xlo);
    cudaGetSymbolAddress(&p_wthi, g_wthi);
    cudaGetSymbolAddress(&p_wtlo, g_wtlo);
    cudaGetSymbolAddress(&p_rthi, g_rthi);
    cudaGetSymbolAddress(&p_rtlo, g_rtlo);
    cudaGetSymbolAddress(&p_xproj, g_xproj);
    cudaGetSymbolAddress(&p_hp, g_hp);
    cudaGetSymbolAddress(&p_hhi, g_hhi);
    cudaGetSymbolAddress(&p_hlo, g_hlo);

    // Prep
    prep_x_kernel<<<MBIG, 128>>>(x);
    prep_w_kernel<<<dim3(G3c / 256, 512), 256>>>(kernel, 0);
    prep_w_kernel<<<dim3(G3c / 256, 512), 256>>>(rkernel, 1);
    zero_h_kernel<<<(Bb * Hh + 255) / 256, 256>>>();

    // Input projection: [65536, 1536] = x @ kernel + bias_i
    gemm_mma<128><<<dim3(G3c / 64, MBIG / 128), 256>>>(
        (const __nv_bfloat16*)p_xhi, (const __nv_bfloat16*)p_xlo,
        (const __nv_bfloat16*)p_wthi, (const __nv_bfloat16*)p_wtlo,
        bias_i, (float*)p_xproj);

    // Recurrence
    int cur = 0;
    for (int t = 0; t < Tt; ++t) {
        gemm_mma<64><<<dim3(G3c / 64, Bb / 64), 256>>>(
            (const __nv_bfloat16*)p_hhi + (size_t)cur * Bb * Hh,
            (const __nv_bfloat16*)p_hlo + (size_t)cur * Bb * Hh,
            (const __nv_bfloat16*)p_rthi, (const __nv_bfloat16*)p_rtlo,
            bias_r, (float*)p_hp);
        gate_kernel<<<(Bb * Hh / 4 + 255) / 256, 256>>>(t, cur);
        cur ^= 1;
    }

    dense_kernel<<<Bb, 128>>>(cur, dense_w, dense_b, out);
}

// round 6
// speedup vs baseline: 2.2166x; 1.2493x over previous
#include <cuda_runtime.h>
#include <cuda_bf16.h>
#include <cstdint>

#define Bb   512
#define Tt   128
#define Ff   512
#define Hh   512
#define G3c  1536
#define MBIG (Bb * Tt)
#define BH   (Bb * Hh)
#define NBLK 128

// ---------------------------------------------------------------------------
// Device-global scratch
// ---------------------------------------------------------------------------
__device__ float g_xproj[(size_t)MBIG * G3c];      // [T*B, 3H], m = t*B + b
__device__ float g_h[BH];                          // final hidden (fp32)
__device__ __nv_bfloat16 g_hhi[2 * BH];            // ping-pong h split hi
__device__ __nv_bfloat16 g_hlo[2 * BH];
__device__ __nv_bfloat16 g_xhi[(size_t)MBIG * Ff];
__device__ __nv_bfloat16 g_xlo[(size_t)MBIG * Ff];
__device__ __nv_bfloat16 g_wthi[G3c * Ff];         // kernel^T  [N=3H, K=F]
__device__ __nv_bfloat16 g_wtlo[G3c * Ff];
__device__ __nv_bfloat16 g_rthi[G3c * Hh];         // rkernel^T [N=3H, K=H]
__device__ __nv_bfloat16 g_rtlo[G3c * Hh];

__device__ unsigned g_bar_count;                   // zero-init
__device__ volatile unsigned g_bar_phase;          // monotonic across replays

// ---------------------------------------------------------------------------
// Helpers
// ---------------------------------------------------------------------------
__device__ __forceinline__ void mma16816(float* d, const uint32_t* a, const uint32_t* b) {
    asm volatile(
        "mma.sync.aligned.m16n8k16.row.col.f32.bf16.bf16.f32 "
        "{%0,%1,%2,%3}, {%4,%5,%6,%7}, {%8,%9}, {%0,%1,%2,%3};"
        : "+f"(d[0]), "+f"(d[1]), "+f"(d[2]), "+f"(d[3])
        : "r"(a[0]), "r"(a[1]), "r"(a[2]), "r"(a[3]), "r"(b[0]), "r"(b[1]));
}
__device__ __forceinline__ void split_bf16(float v, __nv_bfloat16& hi, __nv_bfloat16& lo) {
    hi = __float2bfloat16(v);
    lo = __float2bfloat16(v - __bfloat162float(hi));
}
__device__ __forceinline__ float sigm(float x) { return 1.0f / (1.0f + __expf(-x)); }
__device__ __forceinline__ float tanh_fast(float x) {
    return 1.0f - 2.0f / (__expf(2.0f * x) + 1.0f);
}

__device__ __forceinline__ void grid_bar() {
    __syncthreads();
    if (threadIdx.x == 0) {
        unsigned old = g_bar_phase;
        __threadfence();
        if (atomicAdd(&g_bar_count, 1u) == NBLK - 1) {
            g_bar_count = 0;
            __threadfence();
            atomicAdd((unsigned*)&g_bar_phase, 1u);
        } else {
            while (g_bar_phase == old) { __nanosleep(64); }
            __threadfence();
        }
    }
    __syncthreads();
}

// ---------------------------------------------------------------------------
// Prep kernels
// ---------------------------------------------------------------------------
__global__ void prep_x_kernel(const float* __restrict__ x) {
    int m = blockIdx.x;
    int b = m & (Bb - 1);
    int t = m >> 9;
    const float4 v = ((const float4*)(x + ((size_t)b * Tt + t) * Ff))[threadIdx.x];
    size_t o = (size_t)m * Ff + threadIdx.x * 4;
    __nv_bfloat16 h0, l0, h1, l1, h2, l2, h3, l3;
    split_bf16(v.x, h0, l0); split_bf16(v.y, h1, l1);
    split_bf16(v.z, h2, l2); split_bf16(v.w, h3, l3);
    *(__nv_bfloat162*)(g_xhi + o)     = __nv_bfloat162(h0, h1);
    *(__nv_bfloat162*)(g_xhi + o + 2) = __nv_bfloat162(h2, h3);
    *(__nv_bfloat162*)(g_xlo + o)     = __nv_bfloat162(l0, l1);
    *(__nv_bfloat162*)(g_xlo + o + 2) = __nv_bfloat162(l2, l3);
}

__global__ void prep_w_kernel(const float* __restrict__ W, int which) {
    int n = blockIdx.x * 256 + threadIdx.x;
    int k = blockIdx.y;
    float v = W[(size_t)k * G3c + n];
    __nv_bfloat16 hi, lo;
    split_bf16(v, hi, lo);
    size_t o = (size_t)n * 512 + k;
    if (which == 0) { g_wthi[o] = hi; g_wtlo[o] = lo; }
    else            { g_rthi[o] = hi; g_rtlo[o] = lo; }
}

__global__ void zero_h_kernel() {
    int i = blockIdx.x * blockDim.x + threadIdx.x;
    if (i < BH) {
        g_hhi[i] = __float2bfloat16(0.0f);
        g_hlo[i] = __float2bfloat16(0.0f);
    }
}

// ---------------------------------------------------------------------------
// bf16x3 GEMM on mma.sync for the input projection (BM=128, BN=64, BK=32)
// (proven in R5 — unchanged)
// ---------------------------------------------------------------------------
__global__ void __launch_bounds__(256)
gemm_xproj(const __nv_bfloat16* __restrict__ Ahi,
           const __nv_bfloat16* __restrict__ Alo,
           const __nv_bfloat16* __restrict__ Bhi,
           const __nv_bfloat16* __restrict__ Blo,
           const float* __restrict__ bias,
           float* __restrict__ C)
{
    constexpr int BM = 128, PAD = 40;
    constexpr int WARPS_M = 4, NSPAN = 32, NT = 4;

    __shared__ __align__(128) __nv_bfloat16 sAhi[BM * PAD];
    __shared__ __align__(128) __nv_bfloat16 sAlo[BM * PAD];
    __shared__ __align__(128) __nv_bfloat16 sBhi[64 * PAD];
    __shared__ __align__(128) __nv_bfloat16 sBlo[64 * PAD];

    const int tid = threadIdx.x;
    const int wid = tid >> 5, lane = tid & 31;
    const int wm = wid & (WARPS_M - 1);
    const int wn = wid / WARPS_M;
    const int m0 = blockIdx.y * BM, n0 = blockIdx.x * 64;

    const int lr = lane >> 2;
    const int lc = (lane & 3) * 2;

    float acc[2][NT][4];
#pragma unroll
    for (int i = 0; i < 2; ++i)
#pragma unroll
        for (int j = 0; j < NT; ++j)
#pragma unroll
            for (int q = 0; q < 4; ++q) acc[i][j][q] = 0.0f;

    for (int kb = 0; kb < 16; ++kb) {
        const int k0 = kb * 32;
#pragma unroll
        for (int it = 0; it < 2; ++it) {
            int idx = it * 256 + tid;
            int r = idx >> 2, c = idx & 3;
            size_t go = (size_t)(m0 + r) * 512 + k0 + c * 8;
            *(uint4*)&sAhi[r * PAD + c * 8] = *(const uint4*)(Ahi + go);
            *(uint4*)&sAlo[r * PAD + c * 8] = *(const uint4*)(Alo + go);
        }
        {
            int r = tid >> 2, c = tid & 3;
            size_t go = (size_t)(n0 + r) * 512 + k0 + c * 8;
            *(uint4*)&sBhi[r * PAD + c * 8] = *(const uint4*)(Bhi + go);
            *(uint4*)&sBlo[r * PAD + c * 8] = *(const uint4*)(Blo + go);
        }
        __syncthreads();

#pragma unroll
        for (int ks = 0; ks < 2; ++ks) {
            const int ko = ks * 16 + lc;
            uint32_t ahi[2][4], alo[2][4], bhi[NT][2], blo[NT][2];
#pragma unroll
            for (int mt = 0; mt < 2; ++mt) {
                int o = (wm * 32 + mt * 16 + lr) * PAD + ko;
                ahi[mt][0] = *(const uint32_t*)&sAhi[o];
                ahi[mt][1] = *(const uint32_t*)&sAhi[o + 8 * PAD];
                ahi[mt][2] = *(const uint32_t*)&sAhi[o + 8];
                ahi[mt][3] = *(const uint32_t*)&sAhi[o + 8 * PAD + 8];
                alo[mt][0] = *(const uint32_t*)&sAlo[o];
                alo[mt][1] = *(const uint32_t*)&sAlo[o + 8 * PAD];
                alo[mt][2] = *(const uint32_t*)&sAlo[o + 8];
                alo[mt][3] = *(const uint32_t*)&sAlo[o + 8 * PAD + 8];
            }
#pragma unroll
            for (int nt = 0; nt < NT; ++nt) {
                int o = (wn * NSPAN + nt * 8 + lr) * PAD + ko;
                bhi[nt][0] = *(const uint32_t*)&sBhi[o];
                bhi[nt][1] = *(const uint32_t*)&sBhi[o + 8];
                blo[nt][0] = *(const uint32_t*)&sBlo[o];
                blo[nt][1] = *(const uint32_t*)&sBlo[o + 8];
            }
#pragma unroll
            for (int mt = 0; mt < 2; ++mt)
#pragma unroll
                for (int nt = 0; nt < NT; ++nt) {
                    mma16816(acc[mt][nt], ahi[mt], bhi[nt]);
                    mma16816(acc[mt][nt], ahi[mt], blo[nt]);
                    mma16816(acc[mt][nt], alo[mt], bhi[nt]);
                }
        }
        __syncthreads();
    }

#pragma unroll
    for (int mt = 0; mt < 2; ++mt) {
#pragma unroll
        for (int nt = 0; nt < NT; ++nt) {
            int n = n0 + wn * NSPAN + nt * 8 + (lane & 3) * 2;
            int mA = m0 + wm * 32 + mt * 16 + (lane >> 2);
            int mB = mA + 8;
            float bx = bias[n], by = bias[n + 1];
            float2 o0 = make_float2(acc[mt][nt][0] + bx, acc[mt][nt][1] + by);
            float2 o1 = make_float2(acc[mt][nt][2] + bx, acc[mt][nt][3] + by);
            *(float2*)(C + (size_t)mA * G3c + n) = o0;
            *(float2*)(C + (size_t)mB * G3c + n) = o1;
        }
    }
}

// ---------------------------------------------------------------------------
// Persistent fused recurrence.
// Grid (16, 8): block (j, i) owns batch rows m0=i*64..+64, gate cols n0=j*32..+32.
// B tile (rkernel^T rows for all 3 gates, warp-interleaved) resident in smem.
// Gates computed in registers from accumulators; h_prev slice in registers.
// One global barrier per step.
// ---------------------------------------------------------------------------
#define PAD_A 40
#define PAD_B 520
#define SB_ELEMS (96 * PAD_B)
#define SA_ELEMS (64 * PAD_A)
#define SMEM_PERSIST ((2 * SB_ELEMS + 2 * SA_ELEMS) * 2)

__global__ void __launch_bounds__(256)
gru_persistent(const float* __restrict__ bias_r)
{
    extern __shared__ __align__(128) char smem[];
    __nv_bfloat16* sBhi = (__nv_bfloat16*)smem;
    __nv_bfloat16* sBlo = sBhi + SB_ELEMS;
    __nv_bfloat16* sAhi = sBlo + SB_ELEMS;
    __nv_bfloat16* sAlo = sAhi + SA_ELEMS;

    const int tid  = threadIdx.x;
    const int wid  = tid >> 5, lane = tid & 31;
    const int wm   = wid & 1;        // 2 warps over M
    const int wn   = wid >> 1;       // 4 warps over N
    const int lr   = lane >> 2;
    const int lc   = (lane & 3) * 2;
    const int n0   = blockIdx.x * 32;  // gate-col tile [n0, n0+32)
    const int m0   = blockIdx.y * 64;  // batch-row tile [m0, m0+64)

    // ---- load resident B tile once: 96 interleaved rows x 512 cols ----
    // smem row rr = wn'*24 + g*8 + s  <-  rkernel^T row g*512 + n0 + wn'*8 + s
    for (int idx = tid; idx < 96 * 64; idx += 256) {
        int rr = idx >> 6, c4 = idx & 63;
        int wq = rr / 24, rem = rr % 24;
        int g = rem >> 3, s = rem & 7;
        size_t grow = (size_t)(g * 512 + n0 + wq * 8 + s) * 512 + c4 * 8;
        *(uint4*)&sBhi[rr * PAD_B + c4 * 8] = *(const uint4*)(g_rthi + grow);
        *(uint4*)&sBlo[rr * PAD_B + c4 * 8] = *(const uint4*)(g_rtlo + grow);
    }

    // per-thread fixed output columns (global, within H)
    const int c0g = n0 + wn * 8 + lc;
    const float2 brz = *(const float2*)(bias_r + c0g);
    const float2 brr = *(const float2*)(bias_r + 512 + c0g);
    const float2 brh = *(const float2*)(bias_r + 1024 + c0g);

    // h_prev slice in registers [mt][rp][col01]
    float hprev[2][2][2];
#pragma unroll
    for (int a = 0; a < 2; ++a)
#pragma unroll
        for (int b = 0; b < 2; ++b) { hprev[a][b][0] = 0.0f; hprev[a][b][1] = 0.0f; }

    float acc[2][3][4];
#pragma unroll
    for (int a = 0; a < 2; ++a)
#pragma unroll
        for (int g = 0; g < 3; ++g)
#pragma unroll
            for (int q = 0; q < 4; ++q) acc[a][g][q] = 0.0f;

    const int ar = tid >> 2, ac = tid & 3;   // A staging: row 0..63, chunk 0..3
    __syncthreads();

#pragma unroll 1
    for (int t = 0; t < Tt; ++t) {
        const int cur = t & 1, nxt = cur ^ 1;
        const __nv_bfloat16* Ah = g_hhi + (size_t)cur * BH;
        const __nv_bfloat16* Al = g_hlo + (size_t)cur * BH;

        // prefetch kb=0
        uint4 pah = __ldcg((const uint4*)(Ah + (size_t)(m0 + ar) * 512 + ac * 8));
        uint4 pal = __ldcg((const uint4*)(Al + (size_t)(m0 + ar) * 512 + ac * 8));

#pragma unroll 1
        for (int kb = 0; kb < 16; ++kb) {
            *(uint4*)&sAhi[ar * PAD_A + ac * 8] = pah;
            *(uint4*)&sAlo[ar * PAD_A + ac * 8] = pal;
            __syncthreads();
            if (kb < 15) {
                size_t go = (size_t)(m0 + ar) * 512 + (kb + 1) * 32 + ac * 8;
                pah = __ldcg((const uint4*)(Ah + go));
                pal = __ldcg((const uint4*)(Al + go));
            }
#pragma unroll
            for (int ks = 0; ks < 2; ++ks) {
                const int ko = ks * 16 + lc;
                uint32_t ahi[2][4], alo[2][4], bhi[3][2], blo[3][2];
#pragma unroll
                for (int mt = 0; mt < 2; ++mt) {
                    int o = (wm * 32 + mt * 16 + lr) * PAD_A + ko;
                    ahi[mt][0] = *(const uint32_t*)&sAhi[o];
                    ahi[mt][1] = *(const uint32_t*)&sAhi[o + 8 * PAD_A];
                    ahi[mt][2] = *(const uint32_t*)&sAhi[o + 8];
                    ahi[mt][3] = *(const uint32_t*)&sAhi[o + 8 * PAD_A + 8];
                    alo[mt][0] = *(const uint32_t*)&sAlo[o];
                    alo[mt][1] = *(const uint32_t*)&sAlo[o + 8 * PAD_A];
                    alo[mt][2] = *(const uint32_t*)&sAlo[o + 8];
                    alo[mt][3] = *(const uint32_t*)&sAlo[o + 8 * PAD_A + 8];
                }
#pragma unroll
                for (int g = 0; g < 3; ++g) {
                    int o = (wn * 24 + g * 8 + lr) * PAD_B + kb * 32 + ko;
                    bhi[g][0] = *(const uint32_t*)&sBhi[o];
                    bhi[g][1] = *(const uint32_t*)&sBhi[o + 8];
                    blo[g][0] = *(const uint32_t*)&sBlo[o];
                    blo[g][1] = *(const uint32_t*)&sBlo[o + 8];
                }
#pragma unroll
                for (int mt = 0; mt < 2; ++mt)
#pragma unroll
                    for (int g = 0; g < 3; ++g) {
                        mma16816(acc[mt][g], ahi[mt], bhi[g]);
                        mma16816(acc[mt][g], ahi[mt], blo[g]);
                        mma16816(acc[mt][g], alo[mt], bhi[g]);
                    }
            }
            __syncthreads();
        }

        // ---- fused gate epilogue (all in registers) ----
        const float* xr = g_xproj + (size_t)t * Bb * G3c;
#pragma unroll
        for (int mt = 0; mt < 2; ++mt) {
#pragma unroll
            for (int rp = 0; rp < 2; ++rp) {
                int row = m0 + wm * 32 + mt * 16 + lr + rp * 8;
                const float* xrow = xr + (size_t)row * G3c + c0g;
                float2 xz = *(const float2*)(xrow);
                float2 xg = *(const float2*)(xrow + 512);
                float2 xh = *(const float2*)(xrow + 1024);

                float hpz0 = acc[mt][0][rp * 2 + 0] + brz.x;
                float hpz1 = acc[mt][0][rp * 2 + 1] + brz.y;
                float hpr0 = acc[mt][1][rp * 2 + 0] + brr.x;
                float hpr1 = acc[mt][1][rp * 2 + 1] + brr.y;
                float hph0 = acc[mt][2][rp * 2 + 0] + brh.x;
                float hph1 = acc[mt][2][rp * 2 + 1] + brh.y;

                float z0 = sigm(xz.x + hpz0), r0 = sigm(xg.x + hpr0);
                float c0 = tanh_fast(xh.x + r0 * hph0);
                float h0 = z0 * hprev[mt][rp][0] + (1.0f - z0) * c0;
                float z1 = sigm(xz.y + hpz1), r1 = sigm(xg.y + hpr1);
                float c1 = tanh_fast(xh.y + r1 * hph1);
                float h1 = z1 * hprev[mt][rp][1] + (1.0f - z1) * c1;

                hprev[mt][rp][0] = h0;
                hprev[mt][rp][1] = h1;

                __nv_bfloat16 b0h, b0l, b1h, b1l;
                split_bf16(h0, b0h, b0l);
                split_bf16(h1, b1h, b1l);
                __nv_bfloat162 vh = __nv_bfloat162(b0h, b1h);
                __nv_bfloat162 vl = __nv_bfloat162(b0l, b1l);
                size_t oo = (size_t)nxt * BH + (size_t)row * 512 + c0g;
                __stcg((__nv_bfloat162*)(g_hhi + oo), vh);
                __stcg((__nv_bfloat162*)(g_hlo + oo), vl);

                // reset accumulators for next step
                acc[mt][0][rp * 2] = 0.0f; acc[mt][0][rp * 2 + 1] = 0.0f;
                acc[mt][1][rp * 2] = 0.0f; acc[mt][1][rp * 2 + 1] = 0.0f;
                acc[mt][2][rp * 2] = 0.0f; acc[mt][2][rp * 2 + 1] = 0.0f;
            }
        }

        grid_bar();
    }

    // ---- write final h (fp32) for the dense head ----
#pragma unroll
    for (int mt = 0; mt < 2; ++mt)
#pragma unroll
        for (int rp = 0; rp < 2; ++rp) {
            int row = m0 + wm * 32 + mt * 16 + lr + rp * 8;
            *(float2*)(g_h + (size_t)row * 512 + c0g) =
                make_float2(hprev[mt][rp][0], hprev[mt][rp][1]);
        }
}

// ---------------------------------------------------------------------------
// Dense head
// ---------------------------------------------------------------------------
__global__ void dense_kernel(const float* __restrict__ w,
                             const float* __restrict__ b0,
                             float* __restrict__ out)
{
    __shared__ float red[4];
    int b = blockIdx.x;
    int tid = threadIdx.x;
    const float* hrow = g_h + (size_t)b * Hh;

    float s = 0.0f;
    for (int n = tid; n < Hh; n += 128) s = fmaf(hrow[n], w[n], s);
#pragma unroll
    for (int o = 16; o > 0; o >>= 1) s += __shfl_down_sync(0xffffffffu, s, o);
    if ((tid & 31) == 0) red[tid >> 5] = s;
    __syncthreads();
    if (tid == 0) out[b] = red[0] + red[1] + red[2] + red[3] + b0[0];
}

// ---------------------------------------------------------------------------
// Launch
// ---------------------------------------------------------------------------
extern "C" void kernel_launch(void* const* d_in, const int* in_sizes, int n_in,
                              void* d_out, int out_size)
{
    const float* x       = (const float*)d_in[0];
    const float* kernel  = (const float*)d_in[1];
    const float* rkernel = (const float*)d_in[2];
    const float* bias_i  = (const float*)d_in[3];
    const float* bias_r  = (const float*)d_in[4];
    const float* dense_w = (const float*)d_in[5];
    const float* dense_b = (const float*)d_in[6];
    float* out = (float*)d_out;

    void *p_xhi, *p_xlo, *p_wthi, *p_wtlo, *p_xproj;
    cudaGetSymbolAddress(&p_xhi, g_xhi);
    cudaGetSymbolAddress(&p_xlo, g_xlo);
    cudaGetSymbolAddress(&p_wthi, g_wthi);
    cudaGetSymbolAddress(&p_wtlo, g_wtlo);
    cudaGetSymbolAddress(&p_xproj, g_xproj);

    static bool attr_set = false;
    if (!attr_set) {
        cudaFuncSetAttribute(gru_persistent,
                             cudaFuncAttributeMaxDynamicSharedMemorySize, SMEM_PERSIST);
        attr_set = true;
    }

    // Prep
    prep_x_kernel<<<MBIG, 128>>>(x);
    prep_w_kernel<<<dim3(G3c / 256, 512), 256>>>(kernel, 0);
    prep_w_kernel<<<dim3(G3c / 256, 512), 256>>>(rkernel, 1);
    zero_h_kernel<<<(BH + 255) / 256, 256>>>();

    // Input projection: [65536, 1536] = x @ kernel + bias_i
    gemm_xproj<<<dim3(G3c / 64, MBIG / 128), 256>>>(
        (const __nv_bfloat16*)p_xhi, (const __nv_bfloat16*)p_xlo,
        (const __nv_bfloat16*)p_wthi, (const __nv_bfloat16*)p_wtlo,
        bias_i, (float*)p_xproj);

    // Fused persistent recurrence (all 128 steps)
    gru_persistent<<<dim3(16, 8), 256, SMEM_PERSIST>>>(bias_r);

    dense_kernel<<<Bb, 128>>>(dense_w, dense_b, out);
}

// round 7
// speedup vs baseline: 2.7522x; 1.2417x over previous
#include <cuda_runtime.h>
#include <cuda_bf16.h>
#include <cstdint>

#define Bb   512
#define Tt   128
#define Ff   512
#define Hh   512
#define G3c  1536
#define MBIG (Bb * Tt)
#define BH   (Bb * Hh)

// ---------------------------------------------------------------------------
// Device-global scratch
// ---------------------------------------------------------------------------
__device__ float g_xproj[(size_t)MBIG * G3c];      // [T*B, 3H], m = t*B + b
__device__ float g_h[BH];                          // final hidden (fp32)
__device__ __nv_bfloat16 g_hhi[2 * BH];            // ping-pong h split hi
__device__ __nv_bfloat16 g_hlo[2 * BH];
__device__ __nv_bfloat16 g_xhi[(size_t)MBIG * Ff];
__device__ __nv_bfloat16 g_xlo[(size_t)MBIG * Ff];
__device__ __nv_bfloat16 g_wthi[G3c * Ff];         // kernel^T  [N=3H, K=F]
__device__ __nv_bfloat16 g_wtlo[G3c * Ff];
__device__ __nv_bfloat16 g_rthi[G3c * Hh];         // rkernel^T [N=3H, K=H]
__device__ __nv_bfloat16 g_rtlo[G3c * Hh];

__device__ unsigned g_bar_count[8];                // zero-init
__device__ volatile unsigned g_bar_phase[8];       // monotonic across replays

// ---------------------------------------------------------------------------
// Helpers
// ---------------------------------------------------------------------------
__device__ __forceinline__ void mma16816(float* d, const uint32_t* a, const uint32_t* b) {
    asm volatile(
        "mma.sync.aligned.m16n8k16.row.col.f32.bf16.bf16.f32 "
        "{%0,%1,%2,%3}, {%4,%5,%6,%7}, {%8,%9}, {%0,%1,%2,%3};"
        : "+f"(d[0]), "+f"(d[1]), "+f"(d[2]), "+f"(d[3])
        : "r"(a[0]), "r"(a[1]), "r"(a[2]), "r"(a[3]), "r"(b[0]), "r"(b[1]));
}
__device__ __forceinline__ void split_bf16(float v, __nv_bfloat16& hi, __nv_bfloat16& lo) {
    hi = __float2bfloat16(v);
    lo = __float2bfloat16(v - __bfloat162float(hi));
}
__device__ __forceinline__ float sigm(float x) { return 1.0f / (1.0f + __expf(-x)); }
__device__ __forceinline__ float tanh_fast(float x) {
    return 1.0f - 2.0f / (__expf(2.0f * x) + 1.0f);
}
__device__ __forceinline__ uint32_t smem_u32(const void* p) {
    uint32_t a;
    asm("{ .reg .u64 t; cvta.to.shared.u64 t, %1; cvt.u32.u64 %0, t; }"
        : "=r"(a) : "l"(p));
    return a;
}
__device__ __forceinline__ void cp16(uint32_t s, const void* g) {
    asm volatile("cp.async.cg.shared.global [%0], [%1], 16;" :: "r"(s), "l"(g));
}
__device__ __forceinline__ void cp_commit() {
    asm volatile("cp.async.commit_group;");
}
template <int N>
__device__ __forceinline__ void cp_wait() {
    asm volatile("cp.async.wait_group %0;" :: "n"(N));
}

// ---------------------------------------------------------------------------
// Prep kernels
// ---------------------------------------------------------------------------
__global__ void prep_x_kernel(const float* __restrict__ x) {
    int m = blockIdx.x;
    int b = m & (Bb - 1);
    int t = m >> 9;
    const float4 v = ((const float4*)(x + ((size_t)b * Tt + t) * Ff))[threadIdx.x];
    size_t o = (size_t)m * Ff + threadIdx.x * 4;
    __nv_bfloat16 h0, l0, h1, l1, h2, l2, h3, l3;
    split_bf16(v.x, h0, l0); split_bf16(v.y, h1, l1);
    split_bf16(v.z, h2, l2); split_bf16(v.w, h3, l3);
    *(__nv_bfloat162*)(g_xhi + o)     = __nv_bfloat162(h0, h1);
    *(__nv_bfloat162*)(g_xhi + o + 2) = __nv_bfloat162(h2, h3);
    *(__nv_bfloat162*)(g_xlo + o)     = __nv_bfloat162(l0, l1);
    *(__nv_bfloat162*)(g_xlo + o + 2) = __nv_bfloat162(l2, l3);
}

__global__ void prep_w_kernel(const float* __restrict__ W, int which) {
    int n = blockIdx.x * 256 + threadIdx.x;
    int k = blockIdx.y;
    float v = W[(size_t)k * G3c + n];
    __nv_bfloat16 hi, lo;
    split_bf16(v, hi, lo);
    size_t o = (size_t)n * 512 + k;
    if (which == 0) { g_wthi[o] = hi; g_wtlo[o] = lo; }
    else            { g_rthi[o] = hi; g_rtlo[o] = lo; }
}

__global__ void zero_h_kernel() {
    int i = blockIdx.x * blockDim.x + threadIdx.x;
    if (i < BH) {
        g_hhi[i] = __float2bfloat16(0.0f);
        g_hlo[i] = __float2bfloat16(0.0f);
    }
}

// ---------------------------------------------------------------------------
// Input-projection GEMM, bf16x3 on mma.sync, 2-stage cp.async pipeline.
// BM=128, BN=128, BK=32, 256 threads.
// ---------------------------------------------------------------------------
#define XP_PAD 40
#define XP_A_ELE (128 * XP_PAD)                   // 5120 elements per matrix
#define XP_STAGE_ELE (4 * XP_A_ELE)               // Ahi, Alo, Bhi, Blo
#define XP_SMEM (2 * XP_STAGE_ELE * 2)            // bytes = 81920

__global__ void __launch_bounds__(256)
gemm_xproj(const __nv_bfloat16* __restrict__ Ahi,
           const __nv_bfloat16* __restrict__ Alo,
           const __nv_bfloat16* __restrict__ Bhi,
           const __nv_bfloat16* __restrict__ Blo,
           const float* __restrict__ bias,
           float* __restrict__ C)
{
    extern __shared__ __align__(128) char dsm[];
    const uint32_t sbase = smem_u32(dsm);

    const int tid = threadIdx.x;
    const int wid = tid >> 5, lane = tid & 31;
    const int wm = wid & 3;          // 4 warps over M (32 rows each)
    const int wn = wid >> 2;         // 2 warps over N (64 cols each)
    const int m0 = blockIdx.y * 128, n0 = blockIdx.x * 128;
    const int lr = lane >> 2;
    const int lc = (lane & 3) * 2;

    const int sr = tid >> 2, sc = tid & 3;

    float acc[2][8][4];
#pragma unroll
    for (int i = 0; i < 2; ++i)
#pragma unroll
        for (int j = 0; j < 8; ++j)
#pragma unroll
            for (int q = 0; q < 4; ++q) acc[i][j][q] = 0.0f;

    auto stage_load = [&](int kb, int st) {
        const int k0 = kb * 32;
        const uint32_t sb = sbase + st * (XP_STAGE_ELE * 2);
#pragma unroll
        for (int it = 0; it < 2; ++it) {
            int r = it * 64 + sr;
            uint32_t so = (uint32_t)(r * XP_PAD + sc * 8) * 2;
            size_t ga = (size_t)(m0 + r) * 512 + k0 + sc * 8;
            size_t gb = (size_t)(n0 + r) * 512 + k0 + sc * 8;
            cp16(sb + so,                Ahi + ga);
            cp16(sb + XP_A_ELE * 2 + so, Alo + ga);
            cp16(sb + XP_A_ELE * 4 + so, Bhi + gb);
            cp16(sb + XP_A_ELE * 6 + so, Blo + gb);
        }
        cp_commit();
    };

    stage_load(0, 0);

    for (int kb = 0; kb < 16; ++kb) {
        const int st = kb & 1;
        if (kb < 15) {
            stage_load(kb + 1, st ^ 1);
            cp_wait<1>();
        } else {
            cp_wait<0>();
        }
        __syncthreads();

        const __nv_bfloat16* sp = (const __nv_bfloat16*)(dsm + st * (XP_STAGE_ELE * 2));
        const __nv_bfloat16* sAhi = sp;
        const __nv_bfloat16* sAlo = sp + XP_A_ELE;
        const __nv_bfloat16* sBhi = sp + 2 * XP_A_ELE;
        const __nv_bfloat16* sBlo = sp + 3 * XP_A_ELE;

#pragma unroll
        for (int ks = 0; ks < 2; ++ks) {
            const int ko = ks * 16 + lc;
            uint32_t ahi[2][4], alo[2][4], bhi[8][2], blo[8][2];
#pragma unroll
            for (int mt = 0; mt < 2; ++mt) {
                int o = (wm * 32 + mt * 16 + lr) * XP_PAD + ko;
                ahi[mt][0] = *(const uint32_t*)&sAhi[o];
                ahi[mt][1] = *(const uint32_t*)&sAhi[o + 8 * XP_PAD];
                ahi[mt][2] = *(const uint32_t*)&sAhi[o + 8];
                ahi[mt][3] = *(const uint32_t*)&sAhi[o + 8 * XP_PAD + 8];
                alo[mt][0] = *(const uint32_t*)&sAlo[o];
                alo[mt][1] = *(const uint32_t*)&sAlo[o + 8 * XP_PAD];
                alo[mt][2] = *(const uint32_t*)&sAlo[o + 8];
                alo[mt][3] = *(const uint32_t*)&sAlo[o + 8 * XP_PAD + 8];
            }
#pragma unroll
            for (int nt = 0; nt < 8; ++nt) {
                int o = (wn * 64 + nt * 8 + lr) * XP_PAD + ko;
                bhi[nt][0] = *(const uint32_t*)&sBhi[o];
                bhi[nt][1] = *(const uint32_t*)&sBhi[o + 8];
                blo[nt][0] = *(const uint32_t*)&sBlo[o];
                blo[nt][1] = *(const uint32_t*)&sBlo[o + 8];
            }
#pragma unroll
            for (int mt = 0; mt < 2; ++mt)
#pragma unroll
                for (int nt = 0; nt < 8; ++nt) {
                    mma16816(acc[mt][nt], ahi[mt], bhi[nt]);
                    mma16816(acc[mt][nt], ahi[mt], blo[nt]);
                    mma16816(acc[mt][nt], alo[mt], bhi[nt]);
                }
        }
        __syncthreads();
    }

#pragma unroll
    for (int mt = 0; mt < 2; ++mt) {
#pragma unroll
        for (int nt = 0; nt < 8; ++nt) {
            int n = n0 + wn * 64 + nt * 8 + (lane & 3) * 2;
            int mA = m0 + wm * 32 + mt * 16 + (lane >> 2);
            int mB = mA + 8;
            float bx = bias[n], by = bias[n + 1];
            float2 o0 = make_float2(acc[mt][nt][0] + bx, acc[mt][nt][1] + by);
            float2 o1 = make_float2(acc[mt][nt][2] + bx, acc[mt][nt][3] + by);
            *(float2*)(C + (size_t)mA * G3c + n) = o0;
            *(float2*)(C + (size_t)mB * G3c + n) = o1;
        }
    }
}

// ---------------------------------------------------------------------------
// Persistent fused recurrence. Grid (16, 8). Per-row-group barrier (16 blocks).
// ---------------------------------------------------------------------------
#define PAD_A 40
#define PAD_B 520
#define SB_ELEMS (96 * PAD_B)
#define SA_ELEMS (64 * PAD_A)
#define SMEM_PERSIST ((2 * SB_ELEMS + 4 * SA_ELEMS) * 2)

__global__ void __launch_bounds__(256)
gru_persistent(const float* __restrict__ bias_r)
{
    extern __shared__ __align__(128) char smem[];
    __nv_bfloat16* sBhi = (__nv_bfloat16*)smem;
    __nv_bfloat16* sBlo = sBhi + SB_ELEMS;
    __nv_bfloat16* sA   = sBlo + SB_ELEMS;   // [stage][hi|lo] = 4 x SA_ELEMS
    const uint32_t sA_base = smem_u32(sA);

    const int tid  = threadIdx.x;
    const int wid  = tid >> 5, lane = tid & 31;
    const int wm   = wid & 1;
    const int wn   = wid >> 1;
    const int lr   = lane >> 2;
    const int lc   = (lane & 3) * 2;
    const int n0   = blockIdx.x * 32;
    const int m0   = blockIdx.y * 64;
    const int grp  = blockIdx.y;

    for (int idx = tid; idx < 96 * 64; idx += 256) {
        int rr = idx >> 6, c4 = idx & 63;
        int wq = rr / 24, rem = rr % 24;
        int g = rem >> 3, s = rem & 7;
        size_t grow = (size_t)(g * 512 + n0 + wq * 8 + s) * 512 + c4 * 8;
        *(uint4*)&sBhi[rr * PAD_B + c4 * 8] = *(const uint4*)(g_rthi + grow);
        *(uint4*)&sBlo[rr * PAD_B + c4 * 8] = *(const uint4*)(g_rtlo + grow);
    }

    const int c0g = n0 + wn * 8 + lc;
    const float2 brz = *(const float2*)(bias_r + c0g);
    const float2 brr = *(const float2*)(bias_r + 512 + c0g);
    const float2 brh = *(const float2*)(bias_r + 1024 + c0g);

    float hprev[2][2][2];
#pragma unroll
    for (int a = 0; a < 2; ++a)
#pragma unroll
        for (int b = 0; b < 2; ++b) { hprev[a][b][0] = 0.0f; hprev[a][b][1] = 0.0f; }

    float acc[2][3][4];
#pragma unroll
    for (int a = 0; a < 2; ++a)
#pragma unroll
        for (int g = 0; g < 3; ++g)
#pragma unroll
            for (int q = 0; q < 4; ++q) acc[a][g][q] = 0.0f;

    const int ar = tid >> 2, ac = tid & 3;
    const uint32_t so_thr = (uint32_t)(ar * PAD_A + ac * 8) * 2;
    __syncthreads();

#pragma unroll 1
    for (int t = 0; t < Tt; ++t) {
        const int cur = t & 1, nxt = cur ^ 1;
        const __nv_bfloat16* Ah = g_hhi + (size_t)cur * BH;
        const __nv_bfloat16* Al = g_hlo + (size_t)cur * BH;

        {   // prefetch kb=0 into stage 0
            size_t go = (size_t)(m0 + ar) * 512 + ac * 8;
            cp16(sA_base + so_thr, Ah + go);
            cp16(sA_base + SA_ELEMS * 2 + so_thr, Al + go);
            cp_commit();
        }

#pragma unroll 1
        for (int kb = 0; kb < 16; ++kb) {
            const int st = kb & 1;
            if (kb < 15) {
                const uint32_t sb = sA_base + (uint32_t)((st ^ 1) * 2 * SA_ELEMS) * 2;
                size_t go = (size_t)(m0 + ar) * 512 + (kb + 1) * 32 + ac * 8;
                cp16(sb + so_thr, Ah + go);
                cp16(sb + SA_ELEMS * 2 + so_thr, Al + go);
                cp_commit();
                cp_wait<1>();
            } else {
                cp_wait<0>();
            }
            __syncthreads();

            const __nv_bfloat16* sAhi = sA + st * 2 * SA_ELEMS;
            const __nv_bfloat16* sAlo = sAhi + SA_ELEMS;

#pragma unroll
            for (int ks = 0; ks < 2; ++ks) {
                const int ko = ks * 16 + lc;
                uint32_t ahi[2][4], alo[2][4], bhi[3][2], blo[3][2];
#pragma unroll
                for (int mt = 0; mt < 2; ++mt) {
                    int o = (wm * 32 + mt * 16 + lr) * PAD_A + ko;
                    ahi[mt][0] = *(const uint32_t*)&sAhi[o];
                    ahi[mt][1] = *(const uint32_t*)&sAhi[o + 8 * PAD_A];
                    ahi[mt][2] = *(const uint32_t*)&sAhi[o + 8];
                    ahi[mt][3] = *(const uint32_t*)&sAhi[o + 8 * PAD_A + 8];
                    alo[mt][0] = *(const uint32_t*)&sAlo[o];
                    alo[mt][1] = *(const uint32_t*)&sAlo[o + 8 * PAD_A];
                    alo[mt][2] = *(const uint32_t*)&sAlo[o + 8];
                    alo[mt][3] = *(const uint32_t*)&sAlo[o + 8 * PAD_A + 8];
                }
#pragma unroll
                for (int g = 0; g < 3; ++g) {
                    int o = (wn * 24 + g * 8 + lr) * PAD_B + kb * 32 + ko;
                    bhi[g][0] = *(const uint32_t*)&sBhi[o];
                    bhi[g][1] = *(const uint32_t*)&sBhi[o + 8];
                    blo[g][0] = *(const uint32_t*)&sBlo[o];
                    blo[g][1] = *(const uint32_t*)&sBlo[o + 8];
                }
#pragma unroll
                for (int mt = 0; mt < 2; ++mt)
#pragma unroll
                    for (int g = 0; g < 3; ++g) {
                        mma16816(acc[mt][g], ahi[mt], bhi[g]);
                        mma16816(acc[mt][g], ahi[mt], blo[g]);
                        mma16816(acc[mt][g], alo[mt], bhi[g]);
                    }
            }
            __syncthreads();
        }

        const float* xr = g_xproj + (size_t)t * Bb * G3c;
#pragma unroll
        for (int mt = 0; mt < 2; ++mt) {
#pragma unroll
            for (int rp = 0; rp < 2; ++rp) {
                int row = m0 + wm * 32 + mt * 16 + lr + rp * 8;
                const float* xrow = xr + (size_t)row * G3c + c0g;
                float2 xz = *(const float2*)(xrow);
                float2 xg = *(const float2*)(xrow + 512);
                float2 xh = *(const float2*)(xrow + 1024);

                float hpz0 = acc[mt][0][rp * 2 + 0] + brz.x;
                float hpz1 = acc[mt][0][rp * 2 + 1] + brz.y;
                float hpr0 = acc[mt][1][rp * 2 + 0] + brr.x;
                float hpr1 = acc[mt][1][rp * 2 + 1] + brr.y;
                float hph0 = acc[mt][2][rp * 2 + 0] + brh.x;
                float hph1 = acc[mt][2][rp * 2 + 1] + brh.y;

                float z0 = sigm(xz.x + hpz0), r0 = sigm(xg.x + hpr0);
                float c0 = tanh_fast(xh.x + r0 * hph0);
                float h0 = z0 * hprev[mt][rp][0] + (1.0f - z0) * c0;
                float z1 = sigm(xz.y + hpz1), r1 = sigm(xg.y + hpr1);
                float c1 = tanh_fast(xh.y + r1 * hph1);
                float h1 = z1 * hprev[mt][rp][1] + (1.0f - z1) * c1;

                hprev[mt][rp][0] = h0;
                hprev[mt][rp][1] = h1;

                __nv_bfloat16 b0h, b0l, b1h, b1l;
                split_bf16(h0, b0h, b0l);
                split_bf16(h1, b1h, b1l);
                size_t oo = (size_t)nxt * BH + (size_t)row * 512 + c0g;
                __stcg((__nv_bfloat162*)(g_hhi + oo), __nv_bfloat162(b0h, b1h));
                __stcg((__nv_bfloat162*)(g_hlo + oo), __nv_bfloat162(b0l, b1l));

                acc[mt][0][rp * 2] = 0.0f; acc[mt][0][rp * 2 + 1] = 0.0f;
                acc[mt][1][rp * 2] = 0.0f; acc[mt][1][rp * 2 + 1] = 0.0f;
                acc[mt][2][rp * 2] = 0.0f; acc[mt][2][rp * 2 + 1] = 0.0f;
            }
        }

        __syncthreads();
        if (tid == 0) {
            unsigned old = g_bar_phase[grp];
            __threadfence();
            if (atomicAdd(&g_bar_count[grp], 1u) == 15) {
                g_bar_count[grp] = 0;
                __threadfence();
                atomicAdd((unsigned*)&g_bar_phase[grp], 1u);
            } else {
                while (g_bar_phase[grp] == old) { __nanosleep(32); }
                __threadfence();
            }
        }
        __syncthreads();
    }

#pragma unroll
    for (int mt = 0; mt < 2; ++mt)
#pragma unroll
        for (int rp = 0; rp < 2; ++rp) {
            int row = m0 + wm * 32 + mt * 16 + lr + rp * 8;
            *(float2*)(g_h + (size_t)row * 512 + c0g) =
                make_float2(hprev[mt][rp][0], hprev[mt][rp][1]);
        }
}

// ---------------------------------------------------------------------------
// Dense head
// ---------------------------------------------------------------------------
__global__ void dense_kernel(const float* __restrict__ w,
                             const float* __restrict__ b0,
                             float* __restrict__ out)
{
    __shared__ float red[4];
    int b = blockIdx.x;
    int tid = threadIdx.x;
    const float* hrow = g_h + (size_t)b * Hh;

    float s = 0.0f;
    for (int n = tid; n < Hh; n += 128) s = fmaf(hrow[n], w[n], s);
#pragma unroll
    for (int o = 16; o > 0; o >>= 1) s += __shfl_down_sync(0xffffffffu, s, o);
    if ((tid & 31) == 0) red[tid >> 5] = s;
    __syncthreads();
    if (tid == 0) out[b] = red[0] + red[1] + red[2] + red[3] + b0[0];
}

// ---------------------------------------------------------------------------
// Launch
// ---------------------------------------------------------------------------
extern "C" void kernel_launch(void* const* d_in, const int* in_sizes, int n_in,
                              void* d_out, int out_size)
{
    const float* x       = (const float*)d_in[0];
    const float* kernel  = (const float*)d_in[1];
    const float* rkernel = (const float*)d_in[2];
    const float* bias_i  = (const float*)d_in[3];
    const float* bias_r  = (const float*)d_in[4];
    const float* dense_w = (const float*)d_in[5];
    const float* dense_b = (const float*)d_in[6];
    float* out = (float*)d_out;

    void *p_xhi, *p_xlo, *p_wthi, *p_wtlo, *p_xproj;
    cudaGetSymbolAddress(&p_xhi, g_xhi);
    cudaGetSymbolAddress(&p_xlo, g_xlo);
    cudaGetSymbolAddress(&p_wthi, g_wthi);
    cudaGetSymbolAddress(&p_wtlo, g_wtlo);
    cudaGetSymbolAddress(&p_xproj, g_xproj);

    static bool attr_set = false;
    if (!attr_set) {
        cudaFuncSetAttribute(gru_persistent,
                             cudaFuncAttributeMaxDynamicSharedMemorySize, SMEM_PERSIST);
        cudaFuncSetAttribute(gemm_xproj,
                             cudaFuncAttributeMaxDynamicSharedMemorySize, XP_SMEM);
        attr_set = true;
    }

    prep_x_kernel<<<MBIG, 128>>>(x);
    prep_w_kernel<<<dim3(G3c / 256, 512), 256>>>(kernel, 0);
    prep_w_kernel<<<dim3(G3c / 256, 512), 256>>>(rkernel, 1);
    zero_h_kernel<<<(BH + 255) / 256, 256>>>();

    gemm_xproj<<<dim3(G3c / 128, MBIG / 128), 256, XP_SMEM>>>(
        (const __nv_bfloat16*)p_xhi, (const __nv_bfloat16*)p_xlo,
        (const __nv_bfloat16*)p_wthi, (const __nv_bfloat16*)p_wtlo,
        bias_i, (float*)p_xproj);

    gru_persistent<<<dim3(16, 8), 256, SMEM_PERSIST>>>(bias_r);

    dense_kernel<<<Bb, 128>>>(dense_w, dense_b, out);
}

// round 8
// speedup vs baseline: 4.4517x; 1.6175x over previous
#include <cuda_runtime.h>
#include <cuda_fp16.h>
#include <cstdint>

#define Bb   512
#define Tt   128
#define Ff   512
#define Hh   512
#define G3c  1536
#define MBIG (Bb * Tt)
#define BH   (Bb * Hh)

// ---------------------------------------------------------------------------
// Device-global scratch
// ---------------------------------------------------------------------------
__device__ float g_xproj[(size_t)MBIG * G3c];      // [T*B, 3H], m = t*B + b
__device__ float g_h[BH];                          // final hidden (fp32)
__device__ __half g_hh[2 * BH];                    // ping-pong h (fp16)
__device__ __half g_xh[(size_t)MBIG * Ff];         // x (fp16), [m, f]
__device__ __half g_wt[G3c * Ff];                  // kernel^T  [N=3H, K=F] fp16
__device__ __half g_rt[G3c * Hh];                  // rkernel^T [N=3H, K=H] fp16

__device__ unsigned g_bar_count[8];                // zero-init
__device__ volatile unsigned g_bar_phase[8];       // monotonic across replays

// ---------------------------------------------------------------------------
// Helpers
// ---------------------------------------------------------------------------
__device__ __forceinline__ void mma16816(float* d, const uint32_t* a, const uint32_t* b) {
    asm volatile(
        "mma.sync.aligned.m16n8k16.row.col.f32.f16.f16.f32 "
        "{%0,%1,%2,%3}, {%4,%5,%6,%7}, {%8,%9}, {%0,%1,%2,%3};"
        : "+f"(d[0]), "+f"(d[1]), "+f"(d[2]), "+f"(d[3])
        : "r"(a[0]), "r"(a[1]), "r"(a[2]), "r"(a[3]), "r"(b[0]), "r"(b[1]));
}
__device__ __forceinline__ float sigm(float x) { return 1.0f / (1.0f + __expf(-x)); }
__device__ __forceinline__ float tanh_fast(float x) {
    return 1.0f - 2.0f / (__expf(2.0f * x) + 1.0f);
}
__device__ __forceinline__ uint32_t smem_u32(const void* p) {
    uint32_t a;
    asm("{ .reg .u64 t; cvta.to.shared.u64 t, %1; cvt.u32.u64 %0, t; }"
        : "=r"(a) : "l"(p));
    return a;
}
__device__ __forceinline__ void cp16(uint32_t s, const void* g) {
    asm volatile("cp.async.cg.shared.global [%0], [%1], 16;" :: "r"(s), "l"(g));
}
__device__ __forceinline__ void cp_commit() {
    asm volatile("cp.async.commit_group;");
}
template <int N>
__device__ __forceinline__ void cp_wait() {
    asm volatile("cp.async.wait_group %0;" :: "n"(N));
}

// ---------------------------------------------------------------------------
// Prep kernels
// ---------------------------------------------------------------------------
__global__ void prep_x_kernel(const float* __restrict__ x) {
    int m = blockIdx.x;
    int b = m & (Bb - 1);
    int t = m >> 9;
    const float4 v = ((const float4*)(x + ((size_t)b * Tt + t) * Ff))[threadIdx.x];
    size_t o = (size_t)m * Ff + threadIdx.x * 4;
    *(__half2*)(g_xh + o)     = __floats2half2_rn(v.x, v.y);
    *(__half2*)(g_xh + o + 2) = __floats2half2_rn(v.z, v.w);
}

// Transpose W [512, 1536] fp32 -> out [1536, 512] fp16 via smem tiles.
// grid (48, 16), block (32, 8)
__global__ void prep_w_kernel(const float* __restrict__ W, __half* __restrict__ out) {
    __shared__ float tile[32][33];
    const int nb = blockIdx.x * 32, kb = blockIdx.y * 32;
    const int tx = threadIdx.x, ty = threadIdx.y;
#pragma unroll
    for (int j = 0; j < 4; ++j)
        tile[ty + 8 * j][tx] = W[(size_t)(kb + ty + 8 * j) * G3c + nb + tx];
    __syncthreads();
#pragma unroll
    for (int j = 0; j < 4; ++j)
        out[(size_t)(nb + ty + 8 * j) * 512 + kb + tx] = __float2half(tile[tx][ty + 8 * j]);
}

// ---------------------------------------------------------------------------
// Input-projection GEMM, fp16 single-pass on mma.sync, 2-stage cp.async.
// BM=128, BN=128, BK=32, 256 threads.
// ---------------------------------------------------------------------------
#define XP_PAD 40
#define XP_MAT (128 * XP_PAD)                     // elements per matrix tile
#define XP_STAGE (2 * XP_MAT)                     // A + B
#define XP_SMEM (2 * XP_STAGE * 2)                // bytes = 40960

__global__ void __launch_bounds__(256)
gemm_xproj(const __half* __restrict__ A,
           const __half* __restrict__ B,
           const float* __restrict__ bias,
           float* __restrict__ C)
{
    extern __shared__ __align__(128) char dsm[];
    const uint32_t sbase = smem_u32(dsm);

    const int tid = threadIdx.x;
    const int wid = tid >> 5, lane = tid & 31;
    const int wm = wid & 3;          // 4 warps over M
    const int wn = wid >> 2;         // 2 warps over N
    const int m0 = blockIdx.y * 128, n0 = blockIdx.x * 128;
    const int lr = lane >> 2;
    const int lc = (lane & 3) * 2;

    const int sr = tid >> 2, sc = tid & 3;

    float acc[2][8][4];
#pragma unroll
    for (int i = 0; i < 2; ++i)
#pragma unroll
        for (int j = 0; j < 8; ++j)
#pragma unroll
            for (int q = 0; q < 4; ++q) acc[i][j][q] = 0.0f;

    auto stage_load = [&](int kb, int st) {
        const int k0 = kb * 32;
        const uint32_t sb = sbase + st * (XP_STAGE * 2);
#pragma unroll
        for (int it = 0; it < 2; ++it) {
            int r = it * 64 + sr;
            uint32_t so = (uint32_t)(r * XP_PAD + sc * 8) * 2;
            cp16(sb + so,              A + (size_t)(m0 + r) * 512 + k0 + sc * 8);
            cp16(sb + XP_MAT * 2 + so, B + (size_t)(n0 + r) * 512 + k0 + sc * 8);
        }
        cp_commit();
    };

    stage_load(0, 0);

    for (int kb = 0; kb < 16; ++kb) {
        const int st = kb & 1;
        if (kb < 15) {
            stage_load(kb + 1, st ^ 1);
            cp_wait<1>();
        } else {
            cp_wait<0>();
        }
        __syncthreads();

        const __half* sp = (const __half*)(dsm + st * (XP_STAGE * 2));
        const __half* sA = sp;
        const __half* sB = sp + XP_MAT;

#pragma unroll
        for (int ks = 0; ks < 2; ++ks) {
            const int ko = ks * 16 + lc;
            uint32_t ah[2][4], bh[8][2];
#pragma unroll
            for (int mt = 0; mt < 2; ++mt) {
                int o = (wm * 32 + mt * 16 + lr) * XP_PAD + ko;
                ah[mt][0] = *(const uint32_t*)&sA[o];
                ah[mt][1] = *(const uint32_t*)&sA[o + 8 * XP_PAD];
                ah[mt][2] = *(const uint32_t*)&sA[o + 8];
                ah[mt][3] = *(const uint32_t*)&sA[o + 8 * XP_PAD + 8];
            }
#pragma unroll
            for (int nt = 0; nt < 8; ++nt) {
                int o = (wn * 64 + nt * 8 + lr) * XP_PAD + ko;
                bh[nt][0] = *(const uint32_t*)&sB[o];
                bh[nt][1] = *(const uint32_t*)&sB[o + 8];
            }
#pragma unroll
            for (int mt = 0; mt < 2; ++mt)
#pragma unroll
                for (int nt = 0; nt < 8; ++nt)
                    mma16816(acc[mt][nt], ah[mt], bh[nt]);
        }
        __syncthreads();
    }

#pragma unroll
    for (int mt = 0; mt < 2; ++mt) {
#pragma unroll
        for (int nt = 0; nt < 8; ++nt) {
            int n = n0 + wn * 64 + nt * 8 + (lane & 3) * 2;
            int mA = m0 + wm * 32 + mt * 16 + (lane >> 2);
            int mB = mA + 8;
            float bx = bias[n], by = bias[n + 1];
            float2 o0 = make_float2(acc[mt][nt][0] + bx, acc[mt][nt][1] + by);
            float2 o1 = make_float2(acc[mt][nt][2] + bx, acc[mt][nt][3] + by);
            *(float2*)(C + (size_t)mA * G3c + n) = o0;
            *(float2*)(C + (size_t)mB * G3c + n) = o1;
        }
    }
}

// ---------------------------------------------------------------------------
// Persistent fused recurrence, fp16 single-pass.
// Grid (16, 8): block (j, i) = batch rows i*64..+64, gate cols j*32..+32.
// rkernel B tile resident in smem (fp16, ~100 KB); A staged 4-deep, 1 sync/kb.
// ---------------------------------------------------------------------------
#define PAD_A 40
#define PAD_B 520
#define SB_ELEMS (96 * PAD_B)
#define SA_ELEMS (64 * PAD_A)
#define SMEM_PERSIST ((SB_ELEMS + 4 * SA_ELEMS) * 2)

__global__ void __launch_bounds__(256)
gru_persistent(const float* __restrict__ bias_r)
{
    extern __shared__ __align__(128) char smem[];
    __half* sB = (__half*)smem;
    __half* sA = sB + SB_ELEMS;            // 4 stages x SA_ELEMS
    const uint32_t sA_base = smem_u32(sA);

    const int tid  = threadIdx.x;
    const int wid  = tid >> 5, lane = tid & 31;
    const int wm   = wid & 1;
    const int wn   = wid >> 1;
    const int lr   = lane >> 2;
    const int lc   = (lane & 3) * 2;
    const int n0   = blockIdx.x * 32;
    const int m0   = blockIdx.y * 64;
    const int grp  = blockIdx.y;

    // resident B tile: 96 interleaved rows x 512 cols (fp16)
    for (int idx = tid; idx < 96 * 64; idx += 256) {
        int rr = idx >> 6, c4 = idx & 63;
        int wq = rr / 24, rem = rr % 24;
        int g = rem >> 3, s = rem & 7;
        size_t grow = (size_t)(g * 512 + n0 + wq * 8 + s) * 512 + c4 * 8;
        *(uint4*)&sB[rr * PAD_B + c4 * 8] = *(const uint4*)(g_rt + grow);
    }

    const int c0g = n0 + wn * 8 + lc;
    const float2 brz = *(const float2*)(bias_r + c0g);
    const float2 brr = *(const float2*)(bias_r + 512 + c0g);
    const float2 brh = *(const float2*)(bias_r + 1024 + c0g);

    float hprev[2][2][2];
#pragma unroll
    for (int a = 0; a < 2; ++a)
#pragma unroll
        for (int b = 0; b < 2; ++b) { hprev[a][b][0] = 0.0f; hprev[a][b][1] = 0.0f; }

    float acc[2][3][4];
#pragma unroll
    for (int a = 0; a < 2; ++a)
#pragma unroll
        for (int g = 0; g < 3; ++g)
#pragma unroll
            for (int q = 0; q < 4; ++q) acc[a][g][q] = 0.0f;

    const int ar = tid >> 2, ac = tid & 3;
    const uint32_t so_thr = (uint32_t)(ar * PAD_A + ac * 8) * 2;
    __syncthreads();

#pragma unroll 1
    for (int t = 0; t < Tt; ++t) {
        const int cur = t & 1, nxt = cur ^ 1;

        if (t > 0) {
            const __half* Ah = g_hh + (size_t)cur * BH;
            const size_t arow = (size_t)(m0 + ar) * 512 + ac * 8;

            // prefetch kb=0,1 into stages 0,1
            cp16(sA_base + so_thr, Ah + arow);
            cp_commit();
            cp16(sA_base + (uint32_t)(2 * SA_ELEMS) + so_thr, Ah + arow + 32);
            cp_commit();

#pragma unroll 1
            for (int kb = 0; kb < 16; ++kb) {
                const int st = kb & 3;
                if (kb < 14) {
                    const uint32_t sb = sA_base + (uint32_t)(((kb + 2) & 3) * SA_ELEMS * 2);
                    cp16(sb + so_thr, Ah + arow + (kb + 2) * 32);
                    cp_commit();
                    cp_wait<2>();
                } else if (kb == 14) {
                    cp_wait<1>();
                } else {
                    cp_wait<0>();
                }
                __syncthreads();

                const __half* sAk = sA + st * SA_ELEMS;

#pragma unroll
                for (int ks = 0; ks < 2; ++ks) {
                    const int ko = ks * 16 + lc;
                    uint32_t ah[2][4], bh[3][2];
#pragma unroll
                    for (int mt = 0; mt < 2; ++mt) {
                        int o = (wm * 32 + mt * 16 + lr) * PAD_A + ko;
                        ah[mt][0] = *(const uint32_t*)&sAk[o];
                        ah[mt][1] = *(const uint32_t*)&sAk[o + 8 * PAD_A];
                        ah[mt][2] = *(const uint32_t*)&sAk[o + 8];
                        ah[mt][3] = *(const uint32_t*)&sAk[o + 8 * PAD_A + 8];
                    }
#pragma unroll
                    for (int g = 0; g < 3; ++g) {
                        int o = (wn * 24 + g * 8 + lr) * PAD_B + kb * 32 + ko;
                        bh[g][0] = *(const uint32_t*)&sB[o];
                        bh[g][1] = *(const uint32_t*)&sB[o + 8];
                    }
#pragma unroll
                    for (int mt = 0; mt < 2; ++mt)
#pragma unroll
                        for (int g = 0; g < 3; ++g)
                            mma16816(acc[mt][g], ah[mt], bh[g]);
                }
            }
        }

        // ---- fused gate epilogue (registers only) ----
        const float* xr = g_xproj + (size_t)t * Bb * G3c;
#pragma unroll
        for (int mt = 0; mt < 2; ++mt) {
#pragma unroll
            for (int rp = 0; rp < 2; ++rp) {
                int row = m0 + wm * 32 + mt * 16 + lr + rp * 8;
                const float* xrow = xr + (size_t)row * G3c + c0g;
                float2 xz = *(const float2*)(xrow);
                float2 xg = *(const float2*)(xrow + 512);
                float2 xh = *(const float2*)(xrow + 1024);

                float hpz0 = acc[mt][0][rp * 2 + 0] + brz.x;
                float hpz1 = acc[mt][0][rp * 2 + 1] + brz.y;
                float hpr0 = acc[mt][1][rp * 2 + 0] + brr.x;
                float hpr1 = acc[mt][1][rp * 2 + 1] + brr.y;
                float hph0 = acc[mt][2][rp * 2 + 0] + brh.x;
                float hph1 = acc[mt][2][rp * 2 + 1] + brh.y;

                float z0 = sigm(xz.x + hpz0), r0 = sigm(xg.x + hpr0);
                float c0 = tanh_fast(xh.x + r0 * hph0);
                float h0 = z0 * hprev[mt][rp][0] + (1.0f - z0) * c0;
                float z1 = sigm(xz.y + hpz1), r1 = sigm(xg.y + hpr1);
                float c1 = tanh_fast(xh.y + r1 * hph1);
                float h1 = z1 * hprev[mt][rp][1] + (1.0f - z1) * c1;

                hprev[mt][rp][0] = h0;
                hprev[mt][rp][1] = h1;

                size_t oo = (size_t)nxt * BH + (size_t)row * 512 + c0g;
                __stcg((__half2*)(g_hh + oo), __floats2half2_rn(h0, h1));

                acc[mt][0][rp * 2] = 0.0f; acc[mt][0][rp * 2 + 1] = 0.0f;
                acc[mt][1][rp * 2] = 0.0f; acc[mt][1][rp * 2 + 1] = 0.0f;
                acc[mt][2][rp * 2] = 0.0f; acc[mt][2][rp * 2 + 1] = 0.0f;
            }
        }

        // per-group barrier (16 blocks sharing this batch-row group)
        __syncthreads();
        if (tid == 0) {
            unsigned old = g_bar_phase[grp];
            __threadfence();
            if (atomicAdd(&g_bar_count[grp], 1u) == 15) {
                g_bar_count[grp] = 0;
                __threadfence();
                atomicAdd((unsigned*)&g_bar_phase[grp], 1u);
            } else {
                while (g_bar_phase[grp] == old) { __nanosleep(32); }
                __threadfence();
            }
        }
        __syncthreads();
    }

    // final h (fp32) for the dense head
#pragma unroll
    for (int mt = 0; mt < 2; ++mt)
#pragma unroll
        for (int rp = 0; rp < 2; ++rp) {
            int row = m0 + wm * 32 + mt * 16 + lr + rp * 8;
            *(float2*)(g_h + (size_t)row * 512 + c0g) =
                make_float2(hprev[mt][rp][0], hprev[mt][rp][1]);
        }
}

// ---------------------------------------------------------------------------
// Dense head
// ---------------------------------------------------------------------------
__global__ void dense_kernel(const float* __restrict__ w,
                             const float* __restrict__ b0,
                             float* __restrict__ out)
{
    __shared__ float red[4];
    int b = blockIdx.x;
    int tid = threadIdx.x;
    const float* hrow = g_h + (size_t)b * Hh;

    float s = 0.0f;
    for (int n = tid; n < Hh; n += 128) s = fmaf(hrow[n], w[n], s);
#pragma unroll
    for (int o = 16; o > 0; o >>= 1) s += __shfl_down_sync(0xffffffffu, s, o);
    if ((tid & 31) == 0) red[tid >> 5] = s;
    __syncthreads();
    if (tid == 0) out[b] = red[0] + red[1] + red[2] + red[3] + b0[0];
}

// ---------------------------------------------------------------------------
// Launch
// ---------------------------------------------------------------------------
extern "C" void kernel_launch(void* const* d_in, const int* in_sizes, int n_in,
                              void* d_out, int out_size)
{
    const float* x       = (const float*)d_in[0];
    const float* kernel  = (const float*)d_in[1];
    const float* rkernel = (const float*)d_in[2];
    const float* bias_i  = (const float*)d_in[3];
    const float* bias_r  = (const float*)d_in[4];
    const float* dense_w = (const float*)d_in[5];
    const float* dense_b = (const float*)d_in[6];
    float* out = (float*)d_out;

    void *p_xh, *p_wt, *p_rt, *p_xproj;
    cudaGetSymbolAddress(&p_xh, g_xh);
    cudaGetSymbolAddress(&p_wt, g_wt);
    cudaGetSymbolAddress(&p_rt, g_rt);
    cudaGetSymbolAddress(&p_xproj, g_xproj);

    static bool attr_set = false;
    if (!attr_set) {
        cudaFuncSetAttribute(gru_persistent,
                             cudaFuncAttributeMaxDynamicSharedMemorySize, SMEM_PERSIST);
        cudaFuncSetAttribute(gemm_xproj,
                             cudaFuncAttributeMaxDynamicSharedMemorySize, XP_SMEM);
        attr_set = true;
    }

    prep_x_kernel<<<MBIG, 128>>>(x);
    prep_w_kernel<<<dim3(48, 16), dim3(32, 8)>>>(kernel,  (__half*)p_wt);
    prep_w_kernel<<<dim3(48, 16), dim3(32, 8)>>>(rkernel, (__half*)p_rt);

    gemm_xproj<<<dim3(G3c / 128, MBIG / 128), 256, XP_SMEM>>>(
        (const __half*)p_xh, (const __half*)p_wt, bias_i, (float*)p_xproj);

    gru_persistent<<<dim3(16, 8), 256, SMEM_PERSIST>>>(bias_r);

    dense_kernel<<<Bb, 128>>>(dense_w, dense_b, out);
}

// round 9
// speedup vs baseline: 5.6129x; 1.2608x over previous
#include <cuda_runtime.h>
#include <cuda_fp16.h>
#include <cstdint>

#define Bb   512
#define Tt   128
#define Ff   512
#define Hh   512
#define G3c  1536
#define MBIG (Bb * Tt)
#define BH   (Bb * Hh)

// ---------------------------------------------------------------------------
// Device-global scratch
// ---------------------------------------------------------------------------
__device__ float g_xproj[(size_t)MBIG * G3c];      // [T*B, 3H], m = t*B + b
__device__ float g_h[BH];                          // final hidden (fp32)
__device__ __half g_hh[2 * BH];                    // ping-pong h (fp16)
__device__ __half g_xh[(size_t)MBIG * Ff];         // x (fp16), [m, f]
__device__ __half g_wt[G3c * Ff];                  // kernel^T  [N=3H, K=F]
__device__ __half g_rt[G3c * Hh];                  // rkernel^T [N=3H, K=H]

__device__ unsigned g_done[8 * 16 * 32];           // flag per (group, colblock), 128B apart

// ---------------------------------------------------------------------------
// Helpers
// ---------------------------------------------------------------------------
__device__ __forceinline__ void mma16816(float* d, const uint32_t* a, const uint32_t* b) {
    asm volatile(
        "mma.sync.aligned.m16n8k16.row.col.f32.f16.f16.f32 "
        "{%0,%1,%2,%3}, {%4,%5,%6,%7}, {%8,%9}, {%0,%1,%2,%3};"
        : "+f"(d[0]), "+f"(d[1]), "+f"(d[2]), "+f"(d[3])
        : "r"(a[0]), "r"(a[1]), "r"(a[2]), "r"(a[3]), "r"(b[0]), "r"(b[1]));
}
__device__ __forceinline__ void ldmx4(uint32_t* r, uint32_t addr) {
    asm volatile("ldmatrix.sync.aligned.m8n8.x4.shared.b16 {%0,%1,%2,%3}, [%4];"
                 : "=r"(r[0]), "=r"(r[1]), "=r"(r[2]), "=r"(r[3]) : "r"(addr));
}
__device__ __forceinline__ void ldmx2(uint32_t* r, uint32_t addr) {
    asm volatile("ldmatrix.sync.aligned.m8n8.x2.shared.b16 {%0,%1}, [%2];"
                 : "=r"(r[0]), "=r"(r[1]) : "r"(addr));
}
__device__ __forceinline__ float sigm(float x) { return 1.0f / (1.0f + __expf(-x)); }
__device__ __forceinline__ float tanh_fast(float x) {
    return 1.0f - 2.0f / (__expf(2.0f * x) + 1.0f);
}
__device__ __forceinline__ uint32_t smem_u32(const void* p) {
    uint32_t a;
    asm("{ .reg .u64 t; cvta.to.shared.u64 t, %1; cvt.u32.u64 %0, t; }"
        : "=r"(a) : "l"(p));
    return a;
}
__device__ __forceinline__ void cp16(uint32_t s, const void* g) {
    asm volatile("cp.async.cg.shared.global [%0], [%1], 16;" :: "r"(s), "l"(g));
}
__device__ __forceinline__ void cp_commit() { asm volatile("cp.async.commit_group;"); }
template <int N>
__device__ __forceinline__ void cp_wait() {
    asm volatile("cp.async.wait_group %0;" :: "n"(N));
}

// ---------------------------------------------------------------------------
// Prep kernels
// ---------------------------------------------------------------------------
__global__ void prep_x_kernel(const float* __restrict__ x) {
    int m = blockIdx.x;
    int b = m & (Bb - 1);
    int t = m >> 9;
    const float4 v = ((const float4*)(x + ((size_t)b * Tt + t) * Ff))[threadIdx.x];
    size_t o = (size_t)m * Ff + threadIdx.x * 4;
    *(__half2*)(g_xh + o)     = __floats2half2_rn(v.x, v.y);
    *(__half2*)(g_xh + o + 2) = __floats2half2_rn(v.z, v.w);
}

__global__ void prep_w_kernel(const float* __restrict__ W, __half* __restrict__ out) {
    __shared__ float tile[32][33];
    const int nb = blockIdx.x * 32, kb = blockIdx.y * 32;
    const int tx = threadIdx.x, ty = threadIdx.y;
#pragma unroll
    for (int j = 0; j < 4; ++j)
        tile[ty + 8 * j][tx] = W[(size_t)(kb + ty + 8 * j) * G3c + nb + tx];
    __syncthreads();
#pragma unroll
    for (int j = 0; j < 4; ++j)
        out[(size_t)(nb + ty + 8 * j) * 512 + kb + tx] = __float2half(tile[tx][ty + 8 * j]);
}

// ---------------------------------------------------------------------------
// Input-projection GEMM, fp16 mma.sync + ldmatrix, 2-stage cp.async.
// BM=128, BN=128, BK=32, 256 threads.
// ---------------------------------------------------------------------------
#define XP_PAD 40
#define XP_MAT (128 * XP_PAD)
#define XP_STAGE (2 * XP_MAT)
#define XP_SMEM (2 * XP_STAGE * 2)

__global__ void __launch_bounds__(256)
gemm_xproj(const __half* __restrict__ A,
           const __half* __restrict__ B,
           const float* __restrict__ bias,
           float* __restrict__ C)
{
    extern __shared__ __align__(128) char dsm[];
    const uint32_t sbase = smem_u32(dsm);

    const int tid = threadIdx.x;
    const int wid = tid >> 5, lane = tid & 31;
    const int wm = wid & 3;          // 4 warps over M
    const int wn = wid >> 2;         // 2 warps over N
    const int m0 = blockIdx.y * 128, n0 = blockIdx.x * 128;

    const int sr = tid >> 2, sc = tid & 3;

    // ldmatrix per-lane element offsets (in halves)
    uint32_t a_off[2], b_off[4];
#pragma unroll
    for (int mt = 0; mt < 2; ++mt)
        a_off[mt] = (uint32_t)((wm * 32 + mt * 16 + (lane & 15)) * XP_PAD + (lane >> 4) * 8);
#pragma unroll
    for (int p = 0; p < 4; ++p)
        b_off[p] = (uint32_t)((wn * 64 + p * 16 + (lane >> 4) * 8 + (lane & 7)) * XP_PAD
                              + ((lane & 8) ? 8 : 0));

    float acc[2][8][4];
#pragma unroll
    for (int i = 0; i < 2; ++i)
#pragma unroll
        for (int j = 0; j < 8; ++j)
#pragma unroll
            for (int q = 0; q < 4; ++q) acc[i][j][q] = 0.0f;

    auto stage_load = [&](int kb, int st) {
        const int k0 = kb * 32;
        const uint32_t sb = sbase + st * (XP_STAGE * 2);
#pragma unroll
        for (int it = 0; it < 2; ++it) {
            int r = it * 64 + sr;
            uint32_t so = (uint32_t)(r * XP_PAD + sc * 8) * 2;
            cp16(sb + so,              A + (size_t)(m0 + r) * 512 + k0 + sc * 8);
            cp16(sb + XP_MAT * 2 + so, B + (size_t)(n0 + r) * 512 + k0 + sc * 8);
        }
        cp_commit();
    };

    stage_load(0, 0);

    for (int kb = 0; kb < 16; ++kb) {
        const int st = kb & 1;
        if (kb < 15) { stage_load(kb + 1, st ^ 1); cp_wait<1>(); }
        else         { cp_wait<0>(); }
        __syncthreads();

        const uint32_t stb = sbase + st * (XP_STAGE * 2);

#pragma unroll
        for (int ks = 0; ks < 2; ++ks) {
            const uint32_t ko2 = (uint32_t)(ks * 16) * 2;
            uint32_t ah[2][4], bh[8][2];
#pragma unroll
            for (int mt = 0; mt < 2; ++mt)
                ldmx4(ah[mt], stb + a_off[mt] * 2 + ko2);
#pragma unroll
            for (int p = 0; p < 4; ++p) {
                uint32_t r4[4];
                ldmx4(r4, stb + XP_MAT * 2 + b_off[p] * 2 + ko2);
                bh[2 * p][0] = r4[0]; bh[2 * p][1] = r4[1];
                bh[2 * p + 1][0] = r4[2]; bh[2 * p + 1][1] = r4[3];
            }
#pragma unroll
            for (int mt = 0; mt < 2; ++mt)
#pragma unroll
                for (int nt = 0; nt < 8; ++nt)
                    mma16816(acc[mt][nt], ah[mt], bh[nt]);
        }
        __syncthreads();
    }

#pragma unroll
    for (int mt = 0; mt < 2; ++mt) {
#pragma unroll
        for (int nt = 0; nt < 8; ++nt) {
            int n = n0 + wn * 64 + nt * 8 + (lane & 3) * 2;
            int mA = m0 + wm * 32 + mt * 16 + (lane >> 2);
            int mB = mA + 8;
            float bx = bias[n], by = bias[n + 1];
            float2 o0 = make_float2(acc[mt][nt][0] + bx, acc[mt][nt][1] + by);
            float2 o1 = make_float2(acc[mt][nt][2] + bx, acc[mt][nt][3] + by);
            *(float2*)(C + (size_t)mA * G3c + n) = o0;
            *(float2*)(C + (size_t)mB * G3c + n) = o1;
        }
    }
}

// ---------------------------------------------------------------------------
// Persistent fused recurrence: fp16, ldmatrix, BK=64, flag barrier,
// xproj operands register-prefetched. Grid (16, 8).
// ---------------------------------------------------------------------------
#define PAD_A 72
#define PAD_B 520
#define SB_ELEMS (96 * PAD_B)
#define SA_ELEMS (64 * PAD_A)
#define SMEM_PERSIST ((SB_ELEMS + 4 * SA_ELEMS) * 2)

__global__ void __launch_bounds__(256)
gru_persistent(const float* __restrict__ bias_r)
{
    extern __shared__ __align__(128) char smem[];
    __half* sB = (__half*)smem;
    __half* sA = sB + SB_ELEMS;            // 4 stages x SA_ELEMS
    const uint32_t sB_base = smem_u32(sB);
    const uint32_t sA_base = smem_u32(sA);

    const int tid  = threadIdx.x;
    const int wid  = tid >> 5, lane = tid & 31;
    const int wm   = wid & 1;
    const int wn   = wid >> 1;
    const int lr   = lane >> 2;
    const int lc   = (lane & 3) * 2;
    const int n0   = blockIdx.x * 32;
    const int m0   = blockIdx.y * 64;
    const int grp  = blockIdx.y;

    // resident B tile: 96 interleaved rows x 512 cols (fp16)
    for (int idx = tid; idx < 96 * 64; idx += 256) {
        int rr = idx >> 6, c4 = idx & 63;
        int wq = rr / 24, rem = rr % 24;
        int g = rem >> 3, s = rem & 7;
        size_t grow = (size_t)(g * 512 + n0 + wq * 8 + s) * 512 + c4 * 8;
        *(uint4*)&sB[rr * PAD_B + c4 * 8] = *(const uint4*)(g_rt + grow);
    }

    // ldmatrix per-lane offsets (halves)
    uint32_t a_off[2];
#pragma unroll
    for (int mt = 0; mt < 2; ++mt)
        a_off[mt] = (uint32_t)((wm * 32 + mt * 16 + (lane & 15)) * PAD_A + (lane >> 4) * 8);
    const uint32_t b_off01 = (uint32_t)((wn * 24 + (lane >> 4) * 8 + (lane & 7)) * PAD_B
                                        + ((lane & 8) ? 8 : 0));
    const uint32_t b_off2  = (uint32_t)((wn * 24 + 16 + (lane & 7)) * PAD_B
                                        + ((lane & 8) ? 8 : 0));

    const int c0g = n0 + wn * 8 + lc;
    const float2 brz = *(const float2*)(bias_r + c0g);
    const float2 brr = *(const float2*)(bias_r + 512 + c0g);
    const float2 brh = *(const float2*)(bias_r + 1024 + c0g);

    float hprev[2][2][2];
#pragma unroll
    for (int a = 0; a < 2; ++a)
#pragma unroll
        for (int b = 0; b < 2; ++b) { hprev[a][b][0] = 0.0f; hprev[a][b][1] = 0.0f; }

    float acc[2][3][4];
#pragma unroll
    for (int a = 0; a < 2; ++a)
#pragma unroll
        for (int g = 0; g < 3; ++g)
#pragma unroll
            for (int q = 0; q < 4; ++q) acc[a][g][q] = 0.0f;

    // A staging: 64 rows x 64 halves = 512 16B-chunks, 2 per thread
    const int ar0 = tid >> 3, ac0 = tid & 7;              // chunk tid
    const int ar1 = (tid + 256) >> 3, ac1 = (tid + 256) & 7;
    const uint32_t soA0 = (uint32_t)(ar0 * PAD_A + ac0 * 8) * 2;
    const uint32_t soA1 = (uint32_t)(ar1 * PAD_A + ac1 * 8) * 2;

    // barrier flags
    const unsigned base = *(volatile unsigned*)&g_done[(grp * 16 + blockIdx.x) * 32];

    __syncthreads();

#pragma unroll 1
    for (int t = 0; t < Tt; ++t) {
        const int cur = t & 1, nxt = cur ^ 1;

        // register-prefetch xproj operands for this step (independent of h)
        const float* xr = g_xproj + (size_t)t * Bb * G3c;
        float2 xp[2][2][3];
#pragma unroll
        for (int mt = 0; mt < 2; ++mt)
#pragma unroll
            for (int rp = 0; rp < 2; ++rp) {
                int row = m0 + wm * 32 + mt * 16 + lr + rp * 8;
                const float* xrow = xr + (size_t)row * G3c + c0g;
                xp[mt][rp][0] = __ldcg((const float2*)(xrow));
                xp[mt][rp][1] = __ldcg((const float2*)(xrow + 512));
                xp[mt][rp][2] = __ldcg((const float2*)(xrow + 1024));
            }

        if (t > 0) {
            const __half* Ah = g_hh + (size_t)cur * BH;

            // prefetch kb=0,1 into stages 0,1
#pragma unroll
            for (int pk = 0; pk < 2; ++pk) {
                const uint32_t sb = sA_base + (uint32_t)(pk * SA_ELEMS) * 2;
                cp16(sb + soA0, Ah + (size_t)(m0 + ar0) * 512 + pk * 64 + ac0 * 8);
                cp16(sb + soA1, Ah + (size_t)(m0 + ar1) * 512 + pk * 64 + ac1 * 8);
                cp_commit();
            }

#pragma unroll 1
            for (int kb = 0; kb < 8; ++kb) {
                const int st = kb & 3;
                if (kb < 6) {
                    const uint32_t sb = sA_base + (uint32_t)(((kb + 2) & 3) * SA_ELEMS) * 2;
                    cp16(sb + soA0, Ah + (size_t)(m0 + ar0) * 512 + (kb + 2) * 64 + ac0 * 8);
                    cp16(sb + soA1, Ah + (size_t)(m0 + ar1) * 512 + (kb + 2) * 64 + ac1 * 8);
                    cp_commit();
                    cp_wait<2>();
                } else if (kb == 6) {
                    cp_wait<1>();
                } else {
                    cp_wait<0>();
                }
                __syncthreads();

                const uint32_t stb = sA_base + (uint32_t)(st * SA_ELEMS) * 2;
                const uint32_t kb2 = (uint32_t)(kb * 64) * 2;

#pragma unroll
                for (int ks = 0; ks < 4; ++ks) {
                    const uint32_t ko2 = (uint32_t)(ks * 16) * 2;
                    uint32_t ah[2][4], bh[3][2];
#pragma unroll
                    for (int mt = 0; mt < 2; ++mt)
                        ldmx4(ah[mt], stb + a_off[mt] * 2 + ko2);
                    {
                        uint32_t r4[4];
                        ldmx4(r4, sB_base + b_off01 * 2 + kb2 + ko2);
                        bh[0][0] = r4[0]; bh[0][1] = r4[1];
                        bh[1][0] = r4[2]; bh[1][1] = r4[3];
                        ldmx2(bh[2], sB_base + b_off2 * 2 + kb2 + ko2);
                    }
#pragma unroll
                    for (int mt = 0; mt < 2; ++mt)
#pragma unroll
                        for (int g = 0; g < 3; ++g)
                            mma16816(acc[mt][g], ah[mt], bh[g]);
                }
            }
        }

        // ---- fused gate epilogue (registers only) ----
#pragma unroll
        for (int mt = 0; mt < 2; ++mt) {
#pragma unroll
            for (int rp = 0; rp < 2; ++rp) {
                int row = m0 + wm * 32 + mt * 16 + lr + rp * 8;
                float2 xz = xp[mt][rp][0];
                float2 xg = xp[mt][rp][1];
                float2 xh = xp[mt][rp][2];

                float hpz0 = acc[mt][0][rp * 2 + 0] + brz.x;
                float hpz1 = acc[mt][0][rp * 2 + 1] + brz.y;
                float hpr0 = acc[mt][1][rp * 2 + 0] + brr.x;
                float hpr1 = acc[mt][1][rp * 2 + 1] + brr.y;
                float hph0 = acc[mt][2][rp * 2 + 0] + brh.x;
                float hph1 = acc[mt][2][rp * 2 + 1] + brh.y;

                float z0 = sigm(xz.x + hpz0), r0 = sigm(xg.x + hpr0);
                float c0 = tanh_fast(xh.x + r0 * hph0);
                float h0 = z0 * hprev[mt][rp][0] + (1.0f - z0) * c0;
                float z1 = sigm(xz.y + hpz1), r1 = sigm(xg.y + hpr1);
                float c1 = tanh_fast(xh.y + r1 * hph1);
                float h1 = z1 * hprev[mt][rp][1] + (1.0f - z1) * c1;

                hprev[mt][rp][0] = h0;
                hprev[mt][rp][1] = h1;

                size_t oo = (size_t)nxt * BH + (size_t)row * 512 + c0g;
                __stcg((__half2*)(g_hh + oo), __floats2half2_rn(h0, h1));

                acc[mt][0][rp * 2] = 0.0f; acc[mt][0][rp * 2 + 1] = 0.0f;
                acc[mt][1][rp * 2] = 0.0f; acc[mt][1][rp * 2 + 1] = 0.0f;
                acc[mt][2][rp * 2] = 0.0f; acc[mt][2][rp * 2 + 1] = 0.0f;
            }
        }

        // ---- per-group flag barrier ----
        __syncthreads();
        if (wid == 0) {
            const unsigned target = base + (unsigned)(t + 1);
            if (lane == 0) {
                __threadfence();
                *(volatile unsigned*)&g_done[(grp * 16 + blockIdx.x) * 32] = target;
            }
            if (lane < 16) {
                volatile unsigned* slot = &g_done[(grp * 16 + lane) * 32];
                while ((int)(*slot - target) < 0) { __nanosleep(20); }
                __threadfence();
            }
        }
        __syncthreads();
    }

    // final h (fp32) for the dense head
#pragma unroll
    for (int mt = 0; mt < 2; ++mt)
#pragma unroll
        for (int rp = 0; rp < 2; ++rp) {
            int row = m0 + wm * 32 + mt * 16 + lr + rp * 8;
            *(float2*)(g_h + (size_t)row * 512 + c0g) =
                make_float2(hprev[mt][rp][0], hprev[mt][rp][1]);
        }
}

// ---------------------------------------------------------------------------
// Dense head
// ---------------------------------------------------------------------------
__global__ void dense_kernel(const float* __restrict__ w,
                             const float* __restrict__ b0,
                             float* __restrict__ out)
{
    __shared__ float red[4];
    int b = blockIdx.x;
    int tid = threadIdx.x;
    const float* hrow = g_h + (size_t)b * Hh;

    float s = 0.0f;
    for (int n = tid; n < Hh; n += 128) s = fmaf(hrow[n], w[n], s);
#pragma unroll
    for (int o = 16; o > 0; o >>= 1) s += __shfl_down_sync(0xffffffffu, s, o);
    if ((tid & 31) == 0) red[tid >> 5] = s;
    __syncthreads();
    if (tid == 0) out[b] = red[0] + red[1] + red[2] + red[3] + b0[0];
}

// ---------------------------------------------------------------------------
// Launch
// ---------------------------------------------------------------------------
extern "C" void kernel_launch(void* const* d_in, const int* in_sizes, int n_in,
                              void* d_out, int out_size)
{
    const float* x       = (const float*)d_in[0];
    const float* kernel  = (const float*)d_in[1];
    const float* rkernel = (const float*)d_in[2];
    const float* bias_i  = (const float*)d_in[3];
    const float* bias_r  = (const float*)d_in[4];
    const float* dense_w = (const float*)d_in[5];
    const float* dense_b = (const float*)d_in[6];
    float* out = (float*)d_out;

    void *p_xh, *p_wt, *p_rt, *p_xproj;
    cudaGetSymbolAddress(&p_xh, g_xh);
    cudaGetSymbolAddress(&p_wt, g_wt);
    cudaGetSymbolAddress(&p_rt, g_rt);
    cudaGetSymbolAddress(&p_xproj, g_xproj);

    static bool attr_set = false;
    if (!attr_set) {
        cudaFuncSetAttribute(gru_persistent,
                             cudaFuncAttributeMaxDynamicSharedMemorySize, SMEM_PERSIST);
        cudaFuncSetAttribute(gemm_xproj,
                             cudaFuncAttributeMaxDynamicSharedMemorySize, XP_SMEM);
        attr_set = true;
    }

    prep_x_kernel<<<MBIG, 128>>>(x);
    prep_w_kernel<<<dim3(48, 16), dim3(32, 8)>>>(kernel,  (__half*)p_wt);
    prep_w_kernel<<<dim3(48, 16), dim3(32, 8)>>>(rkernel, (__half*)p_rt);

    gemm_xproj<<<dim3(G3c / 128, MBIG / 128), 256, XP_SMEM>>>(
        (const __half*)p_xh, (const __half*)p_wt, bias_i, (float*)p_xproj);

    gru_persistent<<<dim3(16, 8), 256, SMEM_PERSIST>>>(bias_r);

    dense_kernel<<<Bb, 128>>>(dense_w, dense_b, out);
}